// round 9
// baseline (speedup 1.0000x reference)
#include <cuda_runtime.h>
#include <cuda_bf16.h>
#include <cstdint>

#define NB 16
#define NC 64
#define NH 256
#define NW 256
#define NK 4
#define NO 64
#define HID 17
#define TEMP 34.0f
#define SLOPE 0.2f

// Scratch (device globals; allocation-free rule)
__device__ float g_pooled[NB * NC];
__device__ float g_att[NB * NK];
__device__ __align__(16) __nv_bfloat16 g_awhi[NB * 9 * NO * NC];  // [b][tap][o][c]
__device__ __align__(16) __nv_bfloat16 g_awlo[NB * 9 * NO * NC];
__device__ float g_aggb[NB * NO];
// Pre-split, transposed input: [b][h][w][c], hi/lo planes
__device__ __align__(16) __nv_bfloat16 g_xhi[(size_t)NB * NH * NW * NC];
__device__ __align__(16) __nv_bfloat16 g_xlo[(size_t)NB * NH * NW * NC];

__device__ __forceinline__ unsigned smem_u32(const void* p) {
    unsigned a;
    asm("{ .reg .u64 t; cvta.to.shared.u64 t, %1; cvt.u32.u64 %0, t; }" : "=r"(a) : "l"(p));
    return a;
}
__device__ __forceinline__ void ldmatrix_x4(unsigned& r0, unsigned& r1, unsigned& r2,
                                            unsigned& r3, unsigned addr) {
    asm volatile("ldmatrix.sync.aligned.m8n8.x4.shared.b16 {%0,%1,%2,%3}, [%4];"
                 : "=r"(r0), "=r"(r1), "=r"(r2), "=r"(r3) : "r"(addr));
}
__device__ __forceinline__ void mma16816(float* d, unsigned a0, unsigned a1, unsigned a2,
                                         unsigned a3, unsigned b0, unsigned b1) {
    asm volatile(
        "mma.sync.aligned.m16n8k16.row.col.f32.bf16.bf16.f32 "
        "{%0,%1,%2,%3}, {%4,%5,%6,%7}, {%8,%9}, {%0,%1,%2,%3};"
        : "+f"(d[0]), "+f"(d[1]), "+f"(d[2]), "+f"(d[3])
        : "r"(a0), "r"(a1), "r"(a2), "r"(a3), "r"(b0), "r"(b1));
}
__device__ __forceinline__ void cp16(unsigned dst, const void* src) {
    asm volatile("cp.async.ca.shared.global [%0], [%1], 16;" :: "r"(dst), "l"(src));
}
__device__ __forceinline__ void cp16z(unsigned dst, const void* src, int sz) {
    asm volatile("cp.async.ca.shared.global [%0], [%1], 16, %2;"
                 :: "r"(dst), "l"(src), "r"(sz));
}

// ---------------------------------------------------------------------------
// Kernel 0: split x into bf16 hi/lo planes, transposed to [b][h][w][c].
// ---------------------------------------------------------------------------
#define SPL_STR 66
#define SPL_SMEM (2 * NW * SPL_STR * 2)  // 67584 B

__global__ void __launch_bounds__(256, 1)
split_kernel(const float* __restrict__ x) {
    extern __shared__ __nv_bfloat16 sp[];
    __nv_bfloat16* SH = sp;
    __nv_bfloat16* SL = sp + NW * SPL_STR;
    const int bh = blockIdx.x;
    const int b = bh >> 8, h = bh & 255;
    const int tid = threadIdx.x;  // = w
    const float* xb = x + ((size_t)b * NC * NH + h) * NW;
#pragma unroll 4
    for (int c = 0; c < NC; c++) {
        float v = xb[(size_t)c * (NH * NW) + tid];
        __nv_bfloat16 hi = __float2bfloat16(v);
        __nv_bfloat16 lo = __float2bfloat16(v - __bfloat162float(hi));
        SH[tid * SPL_STR + c] = hi;
        SL[tid * SPL_STR + c] = lo;
    }
    __syncthreads();
    unsigned* oh = (unsigned*)(g_xhi + (size_t)bh * NW * NC);
    unsigned* ol = (unsigned*)(g_xlo + (size_t)bh * NW * NC);
    const unsigned* sh32 = (const unsigned*)SH;
    const unsigned* sl32 = (const unsigned*)SL;
#pragma unroll
    for (int i = tid; i < NW * 32; i += 256) {
        int w = i >> 5, c2 = i & 31;
        oh[w * 32 + c2] = sh32[w * 33 + c2];
        ol[w * 32 + c2] = sl32[w * 33 + c2];
    }
}

// ---------------------------------------------------------------------------
// Kernel 1: global average pool
// ---------------------------------------------------------------------------
__global__ void pool_kernel(const float* __restrict__ x) {
    int bc = blockIdx.x;
    const float4* p = reinterpret_cast<const float4*>(x) + (size_t)bc * (NH * NW / 4);
    float s = 0.f;
    for (int i = threadIdx.x; i < NH * NW / 4; i += 256) {
        float4 v = p[i];
        s += (v.x + v.y) + (v.z + v.w);
    }
#pragma unroll
    for (int off = 16; off; off >>= 1) s += __shfl_down_sync(0xFFFFFFFFu, s, off);
    __shared__ float ws[8];
    if ((threadIdx.x & 31) == 0) ws[threadIdx.x >> 5] = s;
    __syncthreads();
    if (threadIdx.x == 0) {
        float tot = 0.f;
#pragma unroll
        for (int w = 0; w < 8; w++) tot += ws[w];
        g_pooled[bc] = tot * (1.0f / (NH * NW));
    }
}

// ---------------------------------------------------------------------------
// Kernel 2: attention MLP + softmax
// ---------------------------------------------------------------------------
__global__ void att_kernel(const float* __restrict__ fc1,
                           const float* __restrict__ fc2,
                           const float* __restrict__ fc2b) {
    __shared__ float sp[NB * NC];
    __shared__ float sf1[HID * NC];
    __shared__ float sh[NB][HID];
    int t = threadIdx.x;
    for (int i = t; i < NB * NC; i += blockDim.x) sp[i] = g_pooled[i];
    for (int i = t; i < HID * NC; i += blockDim.x) sf1[i] = fc1[i];
    __syncthreads();
    if (t < NB * HID) {
        int b = t / HID, j = t % HID;
        float s = 0.f;
#pragma unroll
        for (int c = 0; c < NC; c++) s += sp[b * NC + c] * sf1[j * NC + c];
        sh[b][j] = s >= 0.f ? s : SLOPE * s;
    }
    __syncthreads();
    if (t < NB) {
        int b = t;
        float lg[NK];
        float m = -1e30f;
#pragma unroll
        for (int k = 0; k < NK; k++) {
            float s = fc2b[k];
#pragma unroll
            for (int j = 0; j < HID; j++) s += sh[b][j] * fc2[k * HID + j];
            lg[k] = s / TEMP;
            m = fmaxf(m, lg[k]);
        }
        float den = 0.f, e[NK];
#pragma unroll
        for (int k = 0; k < NK; k++) { e[k] = expf(lg[k] - m); den += e[k]; }
        float inv = 1.0f / den;
#pragma unroll
        for (int k = 0; k < NK; k++) g_att[b * NK + k] = e[k] * inv;
    }
}

// ---------------------------------------------------------------------------
// Kernel 3: aggregate weights -> split bf16 planes, layout [b][tap][o][c]
// ---------------------------------------------------------------------------
__global__ void agg_kernel(const float* __restrict__ weight,
                           const float* __restrict__ bias_k) {
    int idx = blockIdx.x * 256 + threadIdx.x;
    const int TOT = NB * 9 * NC * NO;
    if (idx < TOT) {
        int c = idx & 63;
        int t1 = idx >> 6;
        int o = t1 & 63;
        int t2 = t1 >> 6;
        int tap = t2 % 9;
        int b = t2 / 9;
        const int KS = NO * NC * 9;
        int wb = (o * NC + c) * 9 + tap;
        float s = g_att[b * NK + 0] * weight[wb] +
                  g_att[b * NK + 1] * weight[wb + KS] +
                  g_att[b * NK + 2] * weight[wb + 2 * KS] +
                  g_att[b * NK + 3] * weight[wb + 3 * KS];
        __nv_bfloat16 hi = __float2bfloat16(s);
        g_awhi[idx] = hi;
        g_awlo[idx] = __float2bfloat16(s - __bfloat162float(hi));
    }
    if (idx < NB * NO) {
        int b = idx >> 6, o = idx & 63;
        float s = 0.f;
#pragma unroll
        for (int k = 0; k < NK; k++) s += g_att[b * NK + k] * bias_k[k * NO + o];
        g_aggb[idx] = s;
    }
}

// ---------------------------------------------------------------------------
// Kernel 4: mma.sync bf16 implicit-GEMM conv. 512 thr, 16 warps (4m x 4n).
// Triple-buffered B (race-free: barrier BEFORE prefetch issue); B via
// ldmatrix.x4; cross-tap A prefetch.
// ---------------------------------------------------------------------------
#define XSTR 72                           // bf16 per row (144 B, conflict-free)
#define XROWS (3 * 130)                   // 390
#define OFF_XH 0
#define OFF_XL (XROWS * XSTR * 2)         // 56160
#define OFF_B (2 * XROWS * XSTR * 2)      // 112320
#define BPLANE (64 * XSTR * 2)            // 9216 B
#define NBUF 3
#define CONV_SMEM (OFF_B + NBUF * 2 * BPLANE)  // 167616

__global__ void __launch_bounds__(512, 1)
conv_kernel(float* __restrict__ out) {
    extern __shared__ char smem[];
    const unsigned sb = smem_u32(smem);
    const int tid = threadIdx.x;
    const int lane = tid & 31, wid = tid >> 5;
    const int wm = wid & 3, wn = wid >> 2;
    const int b = blockIdx.y;
    const int y = blockIdx.x >> 1;
    const int x0 = (blockIdx.x & 1) * 128;

    // ---- stage X via cp.async (hi/lo planes, halo zero-filled) ----
    {
        const size_t bbase = (size_t)b * NH * NW * NC;
        for (int i = tid; i < XROWS * 16; i += 512) {
            int row = i >> 4;
            int rem = i & 15;
            int plane = rem >> 3, ck = rem & 7;
            int r = row / 130, col = row - r * 130;
            int gy = y - 1 + r, gx = x0 - 1 + col;
            bool ok = ((unsigned)gy < 256u) && ((unsigned)gx < 256u);
            const __nv_bfloat16* base = plane ? g_xlo : g_xhi;
            const void* src = base + bbase + (((size_t)gy * NW + (ok ? gx : 0)) * NC) + ck * 8;
            unsigned dst = sb + (plane ? OFF_XL : OFF_XH) + row * (XSTR * 2) + ck * 16;
            cp16z(dst, src, ok ? 16 : 0);
        }
        asm volatile("cp.async.commit_group;");
    }

    // ---- B staging (cp.async into one of 3 buffers) ----
    const __nv_bfloat16* awh = g_awhi + (size_t)b * 9 * (NO * NC);
    const __nv_bfloat16* awl = g_awlo + (size_t)b * 9 * (NO * NC);
#define STAGE_B(TAP, BUF)                                                        \
    {                                                                            \
        _Pragma("unroll")                                                        \
        for (int j = 0; j < 2; j++) {                                            \
            int q = tid + j * 512;                                               \
            int plane = q >> 9, rem = q & 511;                                   \
            int o = rem >> 3, ck = rem & 7;                                      \
            const __nv_bfloat16* srcb = plane ? awl : awh;                       \
            const void* src = srcb + ((TAP) * NO + o) * NC + ck * 8;             \
            unsigned dst = sb + OFF_B + (BUF) * 2 * BPLANE + plane * BPLANE +    \
                           o * (XSTR * 2) + ck * 16;                             \
            cp16(dst, src);                                                      \
        }                                                                        \
        asm volatile("cp.async.commit_group;");                                  \
    }

    STAGE_B(0, 0);
    STAGE_B(1, 1);

    float acc[2][2][4];
#pragma unroll
    for (int mt = 0; mt < 2; mt++)
#pragma unroll
        for (int tn = 0; tn < 2; tn++)
#pragma unroll
            for (int r = 0; r < 4; r++) acc[mt][tn][r] = 0.f;

    const unsigned sXH = sb + OFF_XH;
    const unsigned sXL = sb + OFF_XL;
    const int acolb = (lane & 16) ? 16 : 0;
    // B ldmatrix lane mapping: quad q = lane>>3; rows = n, 16B halves = k
    const int bq = lane >> 3;
    const int brow = wn * 16 + ((bq & 2) << 2) + (lane & 7);
    const unsigned bqoff = (unsigned)((bq & 1) * 16);

    unsigned hc[8], lc[8], hn[8], ln[8];

#pragma unroll 1
    for (int tap = 0; tap < 9; tap++) {
        const int buf = tap % 3;
        if (tap == 8) asm volatile("cp.async.wait_group 0;");
        else          asm volatile("cp.async.wait_group 1;");
        __syncthreads();  // all warps done with tap-1 compute; B(tap) visible
        if (tap < 7) STAGE_B(tap + 2, (tap + 2) % 3);  // safe: after barrier

        const int ky = tap / 3, kx = tap % 3;
        const unsigned abase =
            (unsigned)((ky * 130 + kx + wm * 32 + (lane & 15)) * (XSTR * 2) + acolb);
        if (tap == 0) {  // prologue A load (X guaranteed resident now)
            ldmatrix_x4(hc[0], hc[1], hc[2], hc[3], sXH + abase);
            ldmatrix_x4(hc[4], hc[5], hc[6], hc[7], sXH + abase + 16 * (XSTR * 2));
            ldmatrix_x4(lc[0], lc[1], lc[2], lc[3], sXL + abase);
            ldmatrix_x4(lc[4], lc[5], lc[6], lc[7], sXL + abase + 16 * (XSTR * 2));
        }

        const unsigned bb = sb + OFF_B + buf * 2 * BPLANE +
                            (unsigned)(brow * (XSTR * 2)) + bqoff;
        unsigned bh[4], bl[4], bhn[4], bln[4];
        ldmatrix_x4(bh[0], bh[1], bh[2], bh[3], bb);           // BH kc0
        ldmatrix_x4(bl[0], bl[1], bl[2], bl[3], bb + BPLANE);  // BL kc0

#pragma unroll
        for (int kc = 0; kc < 4; kc++) {
            if (kc < 3) {
                unsigned adh = sXH + abase + (unsigned)((kc + 1) * 32);
                unsigned adl = sXL + abase + (unsigned)((kc + 1) * 32);
                ldmatrix_x4(hn[0], hn[1], hn[2], hn[3], adh);
                ldmatrix_x4(hn[4], hn[5], hn[6], hn[7], adh + 16 * (XSTR * 2));
                ldmatrix_x4(ln[0], ln[1], ln[2], ln[3], adl);
                ldmatrix_x4(ln[4], ln[5], ln[6], ln[7], adl + 16 * (XSTR * 2));
                ldmatrix_x4(bhn[0], bhn[1], bhn[2], bhn[3], bb + (kc + 1) * 32);
                ldmatrix_x4(bln[0], bln[1], bln[2], bln[3], bb + BPLANE + (kc + 1) * 32);
            } else if (tap < 8) {
                // cross-tap A prefetch (X is read-only; safe across barrier)
                const int ky2 = (tap + 1) / 3, kx2 = (tap + 1) % 3;
                const unsigned ab2 = (unsigned)(
                    (ky2 * 130 + kx2 + wm * 32 + (lane & 15)) * (XSTR * 2) + acolb);
                ldmatrix_x4(hn[0], hn[1], hn[2], hn[3], sXH + ab2);
                ldmatrix_x4(hn[4], hn[5], hn[6], hn[7], sXH + ab2 + 16 * (XSTR * 2));
                ldmatrix_x4(ln[0], ln[1], ln[2], ln[3], sXL + ab2);
                ldmatrix_x4(ln[4], ln[5], ln[6], ln[7], sXL + ab2 + 16 * (XSTR * 2));
            }
#pragma unroll
            for (int tn = 0; tn < 2; tn++) {
                unsigned b0h = bh[tn * 2], b1h = bh[tn * 2 + 1];
                unsigned b0l = bl[tn * 2], b1l = bl[tn * 2 + 1];
                mma16816(acc[0][tn], hc[0], hc[1], hc[2], hc[3], b0h, b1h);
                mma16816(acc[1][tn], hc[4], hc[5], hc[6], hc[7], b0h, b1h);
                mma16816(acc[0][tn], lc[0], lc[1], lc[2], lc[3], b0h, b1h);
                mma16816(acc[1][tn], lc[4], lc[5], lc[6], lc[7], b0h, b1h);
                mma16816(acc[0][tn], hc[0], hc[1], hc[2], hc[3], b0l, b1l);
                mma16816(acc[1][tn], hc[4], hc[5], hc[6], hc[7], b0l, b1l);
            }
#pragma unroll
            for (int r = 0; r < 8; r++) { hc[r] = hn[r]; lc[r] = ln[r]; }
#pragma unroll
            for (int r = 0; r < 4; r++) { bh[r] = bhn[r]; bl[r] = bln[r]; }
        }
    }

    // ---- epilogue: bias + store ----
#pragma unroll
    for (int mt = 0; mt < 2; mt++) {
        int m0 = x0 + wm * 32 + mt * 16 + (lane >> 2);
#pragma unroll
        for (int tn = 0; tn < 2; tn++) {
            int n0 = wn * 16 + tn * 8 + (lane & 3) * 2;
            float bv0 = g_aggb[b * NO + n0];
            float bv1 = g_aggb[b * NO + n0 + 1];
            size_t p0 = ((size_t)(b * NO + n0) * NH + y) * NW;
            size_t p1 = ((size_t)(b * NO + n0 + 1) * NH + y) * NW;
            out[p0 + m0] = acc[mt][tn][0] + bv0;
            out[p1 + m0] = acc[mt][tn][1] + bv1;
            out[p0 + m0 + 8] = acc[mt][tn][2] + bv0;
            out[p1 + m0 + 8] = acc[mt][tn][3] + bv1;
        }
    }
#undef STAGE_B
}

// ---------------------------------------------------------------------------
extern "C" void kernel_launch(void* const* d_in, const int* in_sizes, int n_in,
                              void* d_out, int out_size) {
    const float* x      = (const float*)d_in[0];
    const float* fc1_w  = (const float*)d_in[1];
    const float* fc2_w  = (const float*)d_in[2];
    const float* fc2_b  = (const float*)d_in[3];
    const float* weight = (const float*)d_in[4];
    const float* bias_k = (const float*)d_in[5];
    float* out = (float*)d_out;

    cudaFuncSetAttribute(split_kernel, cudaFuncAttributeMaxDynamicSharedMemorySize,
                         SPL_SMEM);
    cudaFuncSetAttribute(conv_kernel, cudaFuncAttributeMaxDynamicSharedMemorySize,
                         CONV_SMEM);

    split_kernel<<<NB * NH, 256, SPL_SMEM>>>(x);
    pool_kernel<<<NB * NC, 256>>>(x);
    att_kernel<<<1, 288>>>(fc1_w, fc2_w, fc2_b);
    agg_kernel<<<(NB * 9 * NC * NO + 255) / 256, 256>>>(weight, bias_k);
    conv_kernel<<<dim3(NH * 2, NB), 512, CONV_SMEM>>>(out);
}

// round 10
// speedup vs baseline: 1.1038x; 1.1038x over previous
#include <cuda_runtime.h>
#include <cuda_bf16.h>
#include <cstdint>

#define NB 16
#define NC 64
#define NH 256
#define NW 256
#define NK 4
#define NO 64
#define HID 17
#define TEMP 34.0f
#define SLOPE 0.2f

// Scratch (device globals; allocation-free rule)
__device__ float g_pooled[NB * NC];
__device__ float g_att[NB * NK];
__device__ __align__(16) __nv_bfloat16 g_awhi[NB * 9 * NO * NC];  // [b][tap][o][c]
__device__ __align__(16) __nv_bfloat16 g_awlo[NB * 9 * NO * NC];
__device__ float g_aggb[NB * NO];
// Pre-split, transposed input: [b][h][w][c], hi/lo planes
__device__ __align__(16) __nv_bfloat16 g_xhi[(size_t)NB * NH * NW * NC];
__device__ __align__(16) __nv_bfloat16 g_xlo[(size_t)NB * NH * NW * NC];

__device__ __forceinline__ unsigned smem_u32(const void* p) {
    unsigned a;
    asm("{ .reg .u64 t; cvta.to.shared.u64 t, %1; cvt.u32.u64 %0, t; }" : "=r"(a) : "l"(p));
    return a;
}
__device__ __forceinline__ void ldmatrix_x4(unsigned& r0, unsigned& r1, unsigned& r2,
                                            unsigned& r3, unsigned addr) {
    asm volatile("ldmatrix.sync.aligned.m8n8.x4.shared.b16 {%0,%1,%2,%3}, [%4];"
                 : "=r"(r0), "=r"(r1), "=r"(r2), "=r"(r3) : "r"(addr));
}
__device__ __forceinline__ void mma16816(float* d, unsigned a0, unsigned a1, unsigned a2,
                                         unsigned a3, unsigned b0, unsigned b1) {
    asm volatile(
        "mma.sync.aligned.m16n8k16.row.col.f32.bf16.bf16.f32 "
        "{%0,%1,%2,%3}, {%4,%5,%6,%7}, {%8,%9}, {%0,%1,%2,%3};"
        : "+f"(d[0]), "+f"(d[1]), "+f"(d[2]), "+f"(d[3])
        : "r"(a0), "r"(a1), "r"(a2), "r"(a3), "r"(b0), "r"(b1));
}
__device__ __forceinline__ void cp16(unsigned dst, const void* src) {
    asm volatile("cp.async.ca.shared.global [%0], [%1], 16;" :: "r"(dst), "l"(src));
}
__device__ __forceinline__ void cp16z(unsigned dst, const void* src, int sz) {
    asm volatile("cp.async.ca.shared.global [%0], [%1], 16, %2;"
                 :: "r"(dst), "l"(src), "r"(sz));
}

// ---------------------------------------------------------------------------
// Kernel 0: split x into bf16 hi/lo planes, transposed to [b][h][w][c].
// ---------------------------------------------------------------------------
#define SPL_STR 66
#define SPL_SMEM (2 * NW * SPL_STR * 2)  // 67584 B

__global__ void __launch_bounds__(256, 1)
split_kernel(const float* __restrict__ x) {
    extern __shared__ __nv_bfloat16 sp[];
    __nv_bfloat16* SH = sp;
    __nv_bfloat16* SL = sp + NW * SPL_STR;
    const int bh = blockIdx.x;
    const int b = bh >> 8, h = bh & 255;
    const int tid = threadIdx.x;  // = w
    const float* xb = x + ((size_t)b * NC * NH + h) * NW;
#pragma unroll 4
    for (int c = 0; c < NC; c++) {
        float v = xb[(size_t)c * (NH * NW) + tid];
        __nv_bfloat16 hi = __float2bfloat16(v);
        __nv_bfloat16 lo = __float2bfloat16(v - __bfloat162float(hi));
        SH[tid * SPL_STR + c] = hi;
        SL[tid * SPL_STR + c] = lo;
    }
    __syncthreads();
    unsigned* oh = (unsigned*)(g_xhi + (size_t)bh * NW * NC);
    unsigned* ol = (unsigned*)(g_xlo + (size_t)bh * NW * NC);
    const unsigned* sh32 = (const unsigned*)SH;
    const unsigned* sl32 = (const unsigned*)SL;
#pragma unroll
    for (int i = tid; i < NW * 32; i += 256) {
        int w = i >> 5, c2 = i & 31;
        oh[w * 32 + c2] = sh32[w * 33 + c2];
        ol[w * 32 + c2] = sl32[w * 33 + c2];
    }
}

// ---------------------------------------------------------------------------
// Kernel 1: global average pool
// ---------------------------------------------------------------------------
__global__ void pool_kernel(const float* __restrict__ x) {
    int bc = blockIdx.x;
    const float4* p = reinterpret_cast<const float4*>(x) + (size_t)bc * (NH * NW / 4);
    float s = 0.f;
    for (int i = threadIdx.x; i < NH * NW / 4; i += 256) {
        float4 v = p[i];
        s += (v.x + v.y) + (v.z + v.w);
    }
#pragma unroll
    for (int off = 16; off; off >>= 1) s += __shfl_down_sync(0xFFFFFFFFu, s, off);
    __shared__ float ws[8];
    if ((threadIdx.x & 31) == 0) ws[threadIdx.x >> 5] = s;
    __syncthreads();
    if (threadIdx.x == 0) {
        float tot = 0.f;
#pragma unroll
        for (int w = 0; w < 8; w++) tot += ws[w];
        g_pooled[bc] = tot * (1.0f / (NH * NW));
    }
}

// ---------------------------------------------------------------------------
// Kernel 2: attention MLP + softmax
// ---------------------------------------------------------------------------
__global__ void att_kernel(const float* __restrict__ fc1,
                           const float* __restrict__ fc2,
                           const float* __restrict__ fc2b) {
    __shared__ float sp[NB * NC];
    __shared__ float sf1[HID * NC];
    __shared__ float sh[NB][HID];
    int t = threadIdx.x;
    for (int i = t; i < NB * NC; i += blockDim.x) sp[i] = g_pooled[i];
    for (int i = t; i < HID * NC; i += blockDim.x) sf1[i] = fc1[i];
    __syncthreads();
    if (t < NB * HID) {
        int b = t / HID, j = t % HID;
        float s = 0.f;
#pragma unroll
        for (int c = 0; c < NC; c++) s += sp[b * NC + c] * sf1[j * NC + c];
        sh[b][j] = s >= 0.f ? s : SLOPE * s;
    }
    __syncthreads();
    if (t < NB) {
        int b = t;
        float lg[NK];
        float m = -1e30f;
#pragma unroll
        for (int k = 0; k < NK; k++) {
            float s = fc2b[k];
#pragma unroll
            for (int j = 0; j < HID; j++) s += sh[b][j] * fc2[k * HID + j];
            lg[k] = s / TEMP;
            m = fmaxf(m, lg[k]);
        }
        float den = 0.f, e[NK];
#pragma unroll
        for (int k = 0; k < NK; k++) { e[k] = expf(lg[k] - m); den += e[k]; }
        float inv = 1.0f / den;
#pragma unroll
        for (int k = 0; k < NK; k++) g_att[b * NK + k] = e[k] * inv;
    }
}

// ---------------------------------------------------------------------------
// Kernel 3: aggregate weights -> split bf16 planes, layout [b][tap][o][c]
// ---------------------------------------------------------------------------
__global__ void agg_kernel(const float* __restrict__ weight,
                           const float* __restrict__ bias_k) {
    int idx = blockIdx.x * 256 + threadIdx.x;
    const int TOT = NB * 9 * NC * NO;
    if (idx < TOT) {
        int c = idx & 63;
        int t1 = idx >> 6;
        int o = t1 & 63;
        int t2 = t1 >> 6;
        int tap = t2 % 9;
        int b = t2 / 9;
        const int KS = NO * NC * 9;
        int wb = (o * NC + c) * 9 + tap;
        float s = g_att[b * NK + 0] * weight[wb] +
                  g_att[b * NK + 1] * weight[wb + KS] +
                  g_att[b * NK + 2] * weight[wb + 2 * KS] +
                  g_att[b * NK + 3] * weight[wb + 3 * KS];
        __nv_bfloat16 hi = __float2bfloat16(s);
        g_awhi[idx] = hi;
        g_awlo[idx] = __float2bfloat16(s - __bfloat162float(hi));
    }
    if (idx < NB * NO) {
        int b = idx >> 6, o = idx & 63;
        float s = 0.f;
#pragma unroll
        for (int k = 0; k < NK; k++) s += g_att[b * NK + k] * bias_k[k * NO + o];
        g_aggb[idx] = s;
    }
}

// ---------------------------------------------------------------------------
// Kernel 4: mma.sync bf16 implicit-GEMM conv. 512 thr, 16 warps (4m x 4n).
// CTA = (b, row-pair, half): 2 output rows x 128 px x 64 out.
// B fragments loaded once per tap, reused by both rows; barriers amortized.
// ---------------------------------------------------------------------------
#define XSTR 72                           // bf16 per row (144 B, conflict-free)
#define XTROWS 4                          // staged X rows: y0-1 .. y0+2
#define XROWS (XTROWS * 130)              // 520
#define OFF_XH 0
#define OFF_XL (XROWS * XSTR * 2)         // 74880
#define OFF_B (2 * XROWS * XSTR * 2)      // 149760
#define BPLANE (64 * XSTR * 2)            // 9216 B
#define NBUF 3
#define CONV_SMEM (OFF_B + NBUF * 2 * BPLANE)  // 205056

__global__ void __launch_bounds__(512, 1)
conv_kernel(float* __restrict__ out) {
    extern __shared__ char smem[];
    const unsigned sb = smem_u32(smem);
    const int tid = threadIdx.x;
    const int lane = tid & 31, wid = tid >> 5;
    const int wm = wid & 3, wn = wid >> 2;
    const int b = blockIdx.y;
    const int y0 = (blockIdx.x >> 1) * 2;       // first output row of the pair
    const int x0 = (blockIdx.x & 1) * 128;

    // ---- stage X via cp.async (hi/lo planes, 4 rows, halo zero-filled) ----
    {
        const size_t bbase = (size_t)b * NH * NW * NC;
        for (int i = tid; i < XROWS * 16; i += 512) {
            int row = i >> 4;
            int rem = i & 15;
            int plane = rem >> 3, ck = rem & 7;
            int r = row / 130, col = row - r * 130;
            int gy = y0 - 1 + r, gx = x0 - 1 + col;
            bool ok = ((unsigned)gy < 256u) && ((unsigned)gx < 256u);
            const __nv_bfloat16* base = plane ? g_xlo : g_xhi;
            const void* src = base + bbase + (((size_t)gy * NW + (ok ? gx : 0)) * NC) + ck * 8;
            unsigned dst = sb + (plane ? OFF_XL : OFF_XH) + row * (XSTR * 2) + ck * 16;
            cp16z(dst, src, ok ? 16 : 0);
        }
        asm volatile("cp.async.commit_group;");
    }

    // ---- B staging (cp.async into one of 3 buffers) ----
    const __nv_bfloat16* awh = g_awhi + (size_t)b * 9 * (NO * NC);
    const __nv_bfloat16* awl = g_awlo + (size_t)b * 9 * (NO * NC);
#define STAGE_B(TAP, BUF)                                                        \
    {                                                                            \
        _Pragma("unroll")                                                        \
        for (int j = 0; j < 2; j++) {                                            \
            int q = tid + j * 512;                                               \
            int plane = q >> 9, rem = q & 511;                                   \
            int o = rem >> 3, ck = rem & 7;                                      \
            const __nv_bfloat16* srcb = plane ? awl : awh;                       \
            const void* src = srcb + ((TAP) * NO + o) * NC + ck * 8;             \
            unsigned dst = sb + OFF_B + (BUF) * 2 * BPLANE + plane * BPLANE +    \
                           o * (XSTR * 2) + ck * 16;                             \
            cp16(dst, src);                                                      \
        }                                                                        \
        asm volatile("cp.async.commit_group;");                                  \
    }

    STAGE_B(0, 0);
    STAGE_B(1, 1);

    float acc[2][2][2][4];  // [row][mt][tn][frag]
#pragma unroll
    for (int rw = 0; rw < 2; rw++)
#pragma unroll
        for (int mt = 0; mt < 2; mt++)
#pragma unroll
            for (int tn = 0; tn < 2; tn++)
#pragma unroll
                for (int r = 0; r < 4; r++) acc[rw][mt][tn][r] = 0.f;

    const unsigned sXH = sb + OFF_XH;
    const unsigned sXL = sb + OFF_XL;
    const int acolb = (lane & 16) ? 16 : 0;
    // B ldmatrix lane mapping (validated): quad q = lane>>3
    const int bq = lane >> 3;
    const int brow = wn * 16 + ((bq & 2) << 2) + (lane & 7);
    const unsigned bqoff = (unsigned)((bq & 1) * 16);

#pragma unroll 1
    for (int tap = 0; tap < 9; tap++) {
        const int buf = tap % 3;
        if (tap == 8) asm volatile("cp.async.wait_group 0;");
        else          asm volatile("cp.async.wait_group 1;");
        __syncthreads();  // all warps done with tap-1 compute; B(tap) visible
        if (tap < 7) STAGE_B(tap + 2, (tap + 2) % 3);  // safe: after barrier

        const int ky = tap / 3, kx = tap % 3;
        const unsigned bb = sb + OFF_B + buf * 2 * BPLANE +
                            (unsigned)(brow * (XSTR * 2)) + bqoff;
        // thread's A pixel base (column within tile)
        const int apix = kx + wm * 32 + (lane & 15);

#pragma unroll
        for (int kc = 0; kc < 4; kc++) {
            unsigned bh[4], bl[4];
            ldmatrix_x4(bh[0], bh[1], bh[2], bh[3], bb + kc * 32);
            ldmatrix_x4(bl[0], bl[1], bl[2], bl[3], bb + BPLANE + kc * 32);
#pragma unroll
            for (int rw = 0; rw < 2; rw++) {
                const unsigned ab =
                    (unsigned)(((rw + ky) * 130 + apix) * (XSTR * 2) + acolb + kc * 32);
                unsigned hc[8], lc[8];
                ldmatrix_x4(hc[0], hc[1], hc[2], hc[3], sXH + ab);
                ldmatrix_x4(hc[4], hc[5], hc[6], hc[7], sXH + ab + 16 * (XSTR * 2));
                ldmatrix_x4(lc[0], lc[1], lc[2], lc[3], sXL + ab);
                ldmatrix_x4(lc[4], lc[5], lc[6], lc[7], sXL + ab + 16 * (XSTR * 2));
#pragma unroll
                for (int tn = 0; tn < 2; tn++) {
                    unsigned b0h = bh[tn * 2], b1h = bh[tn * 2 + 1];
                    unsigned b0l = bl[tn * 2], b1l = bl[tn * 2 + 1];
                    mma16816(acc[rw][0][tn], hc[0], hc[1], hc[2], hc[3], b0h, b1h);
                    mma16816(acc[rw][1][tn], hc[4], hc[5], hc[6], hc[7], b0h, b1h);
                    mma16816(acc[rw][0][tn], lc[0], lc[1], lc[2], lc[3], b0h, b1h);
                    mma16816(acc[rw][1][tn], lc[4], lc[5], lc[6], lc[7], b0h, b1h);
                    mma16816(acc[rw][0][tn], hc[0], hc[1], hc[2], hc[3], b0l, b1l);
                    mma16816(acc[rw][1][tn], hc[4], hc[5], hc[6], hc[7], b0l, b1l);
                }
            }
        }
    }

    // ---- epilogue: bias + store (2 rows) ----
#pragma unroll
    for (int rw = 0; rw < 2; rw++) {
        const int y = y0 + rw;
#pragma unroll
        for (int mt = 0; mt < 2; mt++) {
            int m0 = x0 + wm * 32 + mt * 16 + (lane >> 2);
#pragma unroll
            for (int tn = 0; tn < 2; tn++) {
                int n0 = wn * 16 + tn * 8 + (lane & 3) * 2;
                float bv0 = g_aggb[b * NO + n0];
                float bv1 = g_aggb[b * NO + n0 + 1];
                size_t p0 = ((size_t)(b * NO + n0) * NH + y) * NW;
                size_t p1 = ((size_t)(b * NO + n0 + 1) * NH + y) * NW;
                out[p0 + m0] = acc[rw][mt][tn][0] + bv0;
                out[p1 + m0] = acc[rw][mt][tn][1] + bv1;
                out[p0 + m0 + 8] = acc[rw][mt][tn][2] + bv0;
                out[p1 + m0 + 8] = acc[rw][mt][tn][3] + bv1;
            }
        }
    }
#undef STAGE_B
}

// ---------------------------------------------------------------------------
extern "C" void kernel_launch(void* const* d_in, const int* in_sizes, int n_in,
                              void* d_out, int out_size) {
    const float* x      = (const float*)d_in[0];
    const float* fc1_w  = (const float*)d_in[1];
    const float* fc2_w  = (const float*)d_in[2];
    const float* fc2_b  = (const float*)d_in[3];
    const float* weight = (const float*)d_in[4];
    const float* bias_k = (const float*)d_in[5];
    float* out = (float*)d_out;

    cudaFuncSetAttribute(split_kernel, cudaFuncAttributeMaxDynamicSharedMemorySize,
                         SPL_SMEM);
    cudaFuncSetAttribute(conv_kernel, cudaFuncAttributeMaxDynamicSharedMemorySize,
                         CONV_SMEM);

    split_kernel<<<NB * NH, 256, SPL_SMEM>>>(x);
    pool_kernel<<<NB * NC, 256>>>(x);
    att_kernel<<<1, 288>>>(fc1_w, fc2_w, fc2_b);
    agg_kernel<<<(NB * 9 * NC * NO + 255) / 256, 256>>>(weight, bias_k);
    conv_kernel<<<dim3(NH, NB), 512, CONV_SMEM>>>(out);
}

// round 11
// speedup vs baseline: 1.5083x; 1.3665x over previous
#include <cuda_runtime.h>
#include <cuda_bf16.h>
#include <cstdint>

#define NB 16
#define NC 64
#define NH 256
#define NW 256
#define NK 4
#define NO 64
#define HID 17
#define TEMP 34.0f
#define SLOPE 0.2f

// Scratch (device globals; allocation-free rule)
__device__ float g_pooled[NB * NC];   // zero-init; re-zeroed by att_kernel each call
__device__ float g_att[NB * NK];
// Aggregated split weights, layout [b][ky][o][kx][c]  (k' = kx*64+c contiguous 192)
__device__ __align__(16) __nv_bfloat16 g_awhi[NB * 3 * NO * 3 * NC];
__device__ __align__(16) __nv_bfloat16 g_awlo[NB * 3 * NO * 3 * NC];
__device__ float g_aggb[NB * NO];
// Pre-split, transposed input: [b][h][w][c], hi/lo planes
__device__ __align__(16) __nv_bfloat16 g_xhi[(size_t)NB * NH * NW * NC];
__device__ __align__(16) __nv_bfloat16 g_xlo[(size_t)NB * NH * NW * NC];

__device__ __forceinline__ unsigned smem_u32(const void* p) {
    unsigned a;
    asm("{ .reg .u64 t; cvta.to.shared.u64 t, %1; cvt.u32.u64 %0, t; }" : "=r"(a) : "l"(p));
    return a;
}
__device__ __forceinline__ unsigned sw128(unsigned o) { return o ^ ((o >> 3) & 0x70); }
__device__ __forceinline__ void ldmatrix_x4(unsigned& r0, unsigned& r1, unsigned& r2,
                                            unsigned& r3, unsigned addr) {
    asm volatile("ldmatrix.sync.aligned.m8n8.x4.shared.b16 {%0,%1,%2,%3}, [%4];"
                 : "=r"(r0), "=r"(r1), "=r"(r2), "=r"(r3) : "r"(addr));
}
__device__ __forceinline__ void mma16816(float* d, const unsigned* a, unsigned b0,
                                         unsigned b1) {
    asm volatile(
        "mma.sync.aligned.m16n8k16.row.col.f32.bf16.bf16.f32 "
        "{%0,%1,%2,%3}, {%4,%5,%6,%7}, {%8,%9}, {%0,%1,%2,%3};"
        : "+f"(d[0]), "+f"(d[1]), "+f"(d[2]), "+f"(d[3])
        : "r"(a[0]), "r"(a[1]), "r"(a[2]), "r"(a[3]), "r"(b0), "r"(b1));
}
__device__ __forceinline__ void cp16(unsigned dst, const void* src) {
    asm volatile("cp.async.ca.shared.global [%0], [%1], 16;" :: "r"(dst), "l"(src));
}
__device__ __forceinline__ void cp16z(unsigned dst, const void* src, int sz) {
    asm volatile("cp.async.ca.shared.global [%0], [%1], 16, %2;"
                 :: "r"(dst), "l"(src), "r"(sz));
}

// ---------------------------------------------------------------------------
// Kernel 0: split x into bf16 hi/lo planes [b][h][w][c]  +  fused avg-pool.
// One block per (b,h). g_pooled accumulated via atomicAdd (zeroed by att).
// ---------------------------------------------------------------------------
#define SPL_STR 66
#define SPL_SMEM (2 * NW * SPL_STR * 2)  // 67584 B

__global__ void __launch_bounds__(256)
split_kernel(const float* __restrict__ x) {
    extern __shared__ __nv_bfloat16 sp[];
    __shared__ float psum[NC][8];
    __nv_bfloat16* SH = sp;
    __nv_bfloat16* SL = sp + NW * SPL_STR;
    const int bh = blockIdx.x;
    const int b = bh >> 8;
    const int tid = threadIdx.x;  // = w
    const int wrp = tid >> 5;
    const float* xb = x + ((size_t)b * NC * NH + (bh & 255)) * NW;
#pragma unroll 4
    for (int c = 0; c < NC; c++) {
        float v = xb[(size_t)c * (NH * NW) + tid];
        __nv_bfloat16 hi = __float2bfloat16(v);
        __nv_bfloat16 lo = __float2bfloat16(v - __bfloat162float(hi));
        SH[tid * SPL_STR + c] = hi;
        SL[tid * SPL_STR + c] = lo;
        // fused pool: warp-reduce v over w
#pragma unroll
        for (int off = 16; off; off >>= 1) v += __shfl_down_sync(0xFFFFFFFFu, v, off);
        if ((tid & 31) == 0) psum[c][wrp] = v;
    }
    __syncthreads();
    if (tid < NC) {
        float s = 0.f;
#pragma unroll
        for (int j = 0; j < 8; j++) s += psum[tid][j];
        atomicAdd(&g_pooled[b * NC + tid], s * (1.0f / (NH * NW)));
    }
    unsigned* oh = (unsigned*)(g_xhi + (size_t)bh * NW * NC);
    unsigned* ol = (unsigned*)(g_xlo + (size_t)bh * NW * NC);
    const unsigned* sh32 = (const unsigned*)SH;
    const unsigned* sl32 = (const unsigned*)SL;
#pragma unroll
    for (int i = tid; i < NW * 32; i += 256) {
        int w = i >> 5, c2 = i & 31;
        oh[w * 32 + c2] = sh32[w * 33 + c2];
        ol[w * 32 + c2] = sl32[w * 33 + c2];
    }
}

// ---------------------------------------------------------------------------
// Kernel 2: attention MLP + softmax (also re-zeroes g_pooled for next call)
// ---------------------------------------------------------------------------
__global__ void att_kernel(const float* __restrict__ fc1,
                           const float* __restrict__ fc2,
                           const float* __restrict__ fc2b) {
    __shared__ float sp[NB * NC];
    __shared__ float sf1[HID * NC];
    __shared__ float sh[NB][HID];
    int t = threadIdx.x;
    for (int i = t; i < NB * NC; i += blockDim.x) sp[i] = g_pooled[i];
    for (int i = t; i < HID * NC; i += blockDim.x) sf1[i] = fc1[i];
    __syncthreads();
    for (int i = t; i < NB * NC; i += blockDim.x) g_pooled[i] = 0.f;  // for replay
    if (t < NB * HID) {
        int b = t / HID, j = t % HID;
        float s = 0.f;
#pragma unroll
        for (int c = 0; c < NC; c++) s += sp[b * NC + c] * sf1[j * NC + c];
        sh[b][j] = s >= 0.f ? s : SLOPE * s;
    }
    __syncthreads();
    if (t < NB) {
        int b = t;
        float lg[NK];
        float m = -1e30f;
#pragma unroll
        for (int k = 0; k < NK; k++) {
            float s = fc2b[k];
#pragma unroll
            for (int j = 0; j < HID; j++) s += sh[b][j] * fc2[k * HID + j];
            lg[k] = s / TEMP;
            m = fmaxf(m, lg[k]);
        }
        float den = 0.f, e[NK];
#pragma unroll
        for (int k = 0; k < NK; k++) { e[k] = expf(lg[k] - m); den += e[k]; }
        float inv = 1.0f / den;
#pragma unroll
        for (int k = 0; k < NK; k++) g_att[b * NK + k] = e[k] * inv;
    }
}

// ---------------------------------------------------------------------------
// Kernel 3: aggregate weights -> split bf16, layout [b][ky][o][kx][c]
// ---------------------------------------------------------------------------
__global__ void agg_kernel(const float* __restrict__ weight,  // [K][O][I][3][3]
                           const float* __restrict__ bias_k) {
    int idx = blockIdx.x * 256 + threadIdx.x;
    const int TOT = NB * 3 * NO * 3 * NC;  // 589824
    if (idx < TOT) {
        int c = idx & 63;
        int t1 = idx >> 6;
        int kx = t1 % 3; t1 /= 3;
        int o = t1 & 63; t1 >>= 6;
        int ky = t1 % 3;
        int b = t1 / 3;
        const int KS = NO * NC * 9;
        int wb = (o * NC + c) * 9 + ky * 3 + kx;
        float s = g_att[b * NK + 0] * weight[wb] +
                  g_att[b * NK + 1] * weight[wb + KS] +
                  g_att[b * NK + 2] * weight[wb + 2 * KS] +
                  g_att[b * NK + 3] * weight[wb + 3 * KS];
        __nv_bfloat16 hi = __float2bfloat16(s);
        g_awhi[idx] = hi;
        g_awlo[idx] = __float2bfloat16(s - __bfloat162float(hi));
    }
    if (idx < NB * NO) {
        int b = idx >> 6, o = idx & 63;
        float s = 0.f;
#pragma unroll
        for (int k = 0; k < NK; k++) s += g_att[b * NK + k] * bias_k[k * NO + o];
        g_aggb[idx] = s;
    }
}

// ---------------------------------------------------------------------------
// Kernel 4: mma.sync conv, K'=192 per ky-row. 512 thr, warp grid 8m x 2n.
// CTA = (b, row-pair, half): 2 rows x 128 px x 64 out.
// X: flat [row][px][c] hi/lo planes, SW128-swizzled (contiguous K'-windows).
// B: [o][k'] padded stride 400 B, single buffer per ky.
// ---------------------------------------------------------------------------
#define XPLANE (4 * 130 * 128)            // 66560 B per plane
#define OFF_B (2 * XPLANE)                // 133120
#define BSTR 400                          // bytes per o-row (192*2 + 16 pad)
#define BPL (64 * BSTR)                   // 25600 B per plane
#define CONV_SMEM (OFF_B + 2 * BPL)       // 184320 B

__global__ void __launch_bounds__(512, 1)
conv_kernel(float* __restrict__ out) {
    extern __shared__ char smem[];
    const unsigned sb = smem_u32(smem);
    const int tid = threadIdx.x;
    const int lane = tid & 31, wid = tid >> 5;
    const int wm = wid & 7, wn = wid >> 3;   // 8m x 2n
    const int b = blockIdx.y;
    const int y0 = (blockIdx.x >> 1) * 2;
    const int x0 = (blockIdx.x & 1) * 128;

    // ---- stage X (2 planes x 4 rows x 130 px x 128B, swizzled) ----
    {
        const size_t bbase = (size_t)b * NH * NW * NC;
        for (int i = tid; i < 8320; i += 512) {
            int plane = (i >= 4160) ? 1 : 0;
            int q = i - plane * 4160;
            int ch = q & 7;
            int rc = q >> 3;                    // r*130 + cl
            int r = rc / 130, cl = rc - r * 130;
            int gy = y0 - 1 + r, gx = x0 - 1 + cl;
            bool ok = ((unsigned)gy < 256u) && ((unsigned)gx < 256u);
            const __nv_bfloat16* base = plane ? g_xlo : g_xhi;
            const void* src = base + bbase +
                              ((size_t)(ok ? (gy * 256 + gx) : 0) * 64) + ch * 8;
            unsigned o = (unsigned)(plane * XPLANE + rc * 128 + ch * 16);
            cp16z(sb + sw128(o), src, ok ? 16 : 0);
        }
        asm volatile("cp.async.commit_group;");
    }

    // ---- B staging: 3072 chunks of 16B per ky ----
    const __nv_bfloat16* awh = g_awhi + (size_t)(b * 3) * (NO * 192);
    const __nv_bfloat16* awl = g_awlo + (size_t)(b * 3) * (NO * 192);
#define STAGE_B(KY)                                                              \
    {                                                                            \
        _Pragma("unroll")                                                        \
        for (int j = 0; j < 6; j++) {                                            \
            int q = tid + j * 512;                                               \
            int plane = (q >= 1536) ? 1 : 0;                                     \
            int rem = q - plane * 1536;                                          \
            int o = rem / 24, ck = rem - o * 24;                                 \
            const __nv_bfloat16* srcb = plane ? awl : awh;                       \
            const void* src = srcb + ((KY) * NO + o) * 192 + ck * 8;             \
            unsigned dst = sb + OFF_B + plane * BPL + o * BSTR + ck * 16;        \
            cp16(dst, src);                                                      \
        }                                                                        \
        asm volatile("cp.async.commit_group;");                                  \
    }

    float acc[2][4][4];
#pragma unroll
    for (int rw = 0; rw < 2; rw++)
#pragma unroll
        for (int tn = 0; tn < 4; tn++)
#pragma unroll
            for (int r = 0; r < 4; r++) acc[rw][tn][r] = 0.f;

    // A lane addressing (m16 x k16 tile per x4)
    const int apx = wm * 16 + (lane & 15);
    const unsigned aklo = (lane & 16) ? 16u : 0u;
    // B lane addressing (n16 x k16 per x4; two n-groups for n=32)
    const int bq = lane >> 3;
    const int brow = ((bq & 2) << 2) + (lane & 7);
    const unsigned bklo = (unsigned)((bq & 1) * 16);
    const unsigned bbase0 = sb + OFF_B + (unsigned)((wn * 32 + brow) * BSTR) + bklo;
    const unsigned bbase1 = bbase0 + 16 * BSTR;

#pragma unroll 1
    for (int ky = 0; ky < 3; ky++) {
        if (ky) __syncthreads();              // all warps done reading B(ky-1)
        STAGE_B(ky);
        asm volatile("cp.async.wait_group 0;");
        __syncthreads();                      // B(ky) (and X on ky==0) visible

#pragma unroll 2
        for (int kc = 0; kc < 12; kc++) {
            unsigned bh0[4], bh1[4], bl0[4], bl1[4];
            ldmatrix_x4(bh0[0], bh0[1], bh0[2], bh0[3], bbase0 + kc * 32);
            ldmatrix_x4(bh1[0], bh1[1], bh1[2], bh1[3], bbase1 + kc * 32);
            ldmatrix_x4(bl0[0], bl0[1], bl0[2], bl0[3], bbase0 + BPL + kc * 32);
            ldmatrix_x4(bl1[0], bl1[1], bl1[2], bl1[3], bbase1 + BPL + kc * 32);
#pragma unroll
            for (int rw = 0; rw < 2; rw++) {
                unsigned o_ = (unsigned)(((ky + rw) * 130 + apx) * 128 + kc * 32) + aklo;
                unsigned hc[4], lc[4];
                ldmatrix_x4(hc[0], hc[1], hc[2], hc[3], sb + sw128(o_));
                ldmatrix_x4(lc[0], lc[1], lc[2], lc[3], sb + sw128(o_ + XPLANE));
                // tn 0,1 from group 0; tn 2,3 from group 1
                mma16816(acc[rw][0], hc, bh0[0], bh0[1]);
                mma16816(acc[rw][0], lc, bh0[0], bh0[1]);
                mma16816(acc[rw][0], hc, bl0[0], bl0[1]);
                mma16816(acc[rw][1], hc, bh0[2], bh0[3]);
                mma16816(acc[rw][1], lc, bh0[2], bh0[3]);
                mma16816(acc[rw][1], hc, bl0[2], bl0[3]);
                mma16816(acc[rw][2], hc, bh1[0], bh1[1]);
                mma16816(acc[rw][2], lc, bh1[0], bh1[1]);
                mma16816(acc[rw][2], hc, bl1[0], bl1[1]);
                mma16816(acc[rw][3], hc, bh1[2], bh1[3]);
                mma16816(acc[rw][3], lc, bh1[2], bh1[3]);
                mma16816(acc[rw][3], hc, bl1[2], bl1[3]);
            }
        }
    }

    // ---- epilogue: bias + store (2 rows) ----
    const int m0 = x0 + wm * 16 + (lane >> 2);
#pragma unroll
    for (int rw = 0; rw < 2; rw++) {
        const int y = y0 + rw;
#pragma unroll
        for (int tn = 0; tn < 4; tn++) {
            int n0 = wn * 32 + tn * 8 + (lane & 3) * 2;
            float bv0 = g_aggb[b * NO + n0];
            float bv1 = g_aggb[b * NO + n0 + 1];
            size_t p0 = ((size_t)(b * NO + n0) * NH + y) * NW;
            size_t p1 = ((size_t)(b * NO + n0 + 1) * NH + y) * NW;
            out[p0 + m0] = acc[rw][tn][0] + bv0;
            out[p1 + m0] = acc[rw][tn][1] + bv1;
            out[p0 + m0 + 8] = acc[rw][tn][2] + bv0;
            out[p1 + m0 + 8] = acc[rw][tn][3] + bv1;
        }
    }
#undef STAGE_B
}

// ---------------------------------------------------------------------------
extern "C" void kernel_launch(void* const* d_in, const int* in_sizes, int n_in,
                              void* d_out, int out_size) {
    const float* x      = (const float*)d_in[0];
    const float* fc1_w  = (const float*)d_in[1];
    const float* fc2_w  = (const float*)d_in[2];
    const float* fc2_b  = (const float*)d_in[3];
    const float* weight = (const float*)d_in[4];
    const float* bias_k = (const float*)d_in[5];
    float* out = (float*)d_out;

    cudaFuncSetAttribute(split_kernel, cudaFuncAttributeMaxDynamicSharedMemorySize,
                         SPL_SMEM);
    cudaFuncSetAttribute(conv_kernel, cudaFuncAttributeMaxDynamicSharedMemorySize,
                         CONV_SMEM);

    split_kernel<<<NB * NH, 256, SPL_SMEM>>>(x);
    att_kernel<<<1, 288>>>(fc1_w, fc2_w, fc2_b);
    agg_kernel<<<(NB * 3 * NO * 3 * NC + 255) / 256, 256>>>(weight, bias_k);
    conv_kernel<<<dim3(NH, NB), 512, CONV_SMEM>>>(out);
}

// round 12
// speedup vs baseline: 1.9202x; 1.2731x over previous
#include <cuda_runtime.h>
#include <cuda_fp16.h>
#include <cstdint>

#define NB 16
#define NC 64
#define NH 256
#define NW 256
#define NK 4
#define NO 64
#define HID 17
#define TEMP 34.0f
#define SLOPE 0.2f

// Scratch (device globals; allocation-free rule)
__device__ float g_pooled[NB * NC];   // zero-init; re-zeroed by att_kernel each call
__device__ float g_att[NB * NK];
// Aggregated fp16 weights, layout [b][ky][o][kx][c]  (k' = kx*64+c contiguous 192)
__device__ __align__(16) __half g_awh[NB * 3 * NO * 3 * NC];
__device__ float g_aggb[NB * NO];
// Pre-split, transposed input: [b][h][w][c], fp16 hi/lo planes
__device__ __align__(16) __half g_xhi[(size_t)NB * NH * NW * NC];
__device__ __align__(16) __half g_xlo[(size_t)NB * NH * NW * NC];

__device__ __forceinline__ unsigned smem_u32(const void* p) {
    unsigned a;
    asm("{ .reg .u64 t; cvta.to.shared.u64 t, %1; cvt.u32.u64 %0, t; }" : "=r"(a) : "l"(p));
    return a;
}
__device__ __forceinline__ unsigned sw128(unsigned o) { return o ^ ((o >> 3) & 0x70); }
__device__ __forceinline__ void ldmatrix_x4(unsigned& r0, unsigned& r1, unsigned& r2,
                                            unsigned& r3, unsigned addr) {
    asm volatile("ldmatrix.sync.aligned.m8n8.x4.shared.b16 {%0,%1,%2,%3}, [%4];"
                 : "=r"(r0), "=r"(r1), "=r"(r2), "=r"(r3) : "r"(addr));
}
__device__ __forceinline__ void mma16816(float* d, const unsigned* a, unsigned b0,
                                         unsigned b1) {
    asm volatile(
        "mma.sync.aligned.m16n8k16.row.col.f32.f16.f16.f32 "
        "{%0,%1,%2,%3}, {%4,%5,%6,%7}, {%8,%9}, {%0,%1,%2,%3};"
        : "+f"(d[0]), "+f"(d[1]), "+f"(d[2]), "+f"(d[3])
        : "r"(a[0]), "r"(a[1]), "r"(a[2]), "r"(a[3]), "r"(b0), "r"(b1));
}
__device__ __forceinline__ void cp16(unsigned dst, const void* src) {
    asm volatile("cp.async.ca.shared.global [%0], [%1], 16;" :: "r"(dst), "l"(src));
}
__device__ __forceinline__ void cp16z(unsigned dst, const void* src, int sz) {
    asm volatile("cp.async.ca.shared.global [%0], [%1], 16, %2;"
                 :: "r"(dst), "l"(src), "r"(sz));
}

// ---------------------------------------------------------------------------
// Kernel 0: split x into fp16 hi/lo planes [b][h][w][c]  +  fused avg-pool.
// ---------------------------------------------------------------------------
#define SPL_STR 66
#define SPL_SMEM (2 * NW * SPL_STR * 2)  // 67584 B

__global__ void __launch_bounds__(256)
split_kernel(const float* __restrict__ x) {
    extern __shared__ __half sp[];
    __shared__ float psum[NC][8];
    __half* SH = sp;
    __half* SL = sp + NW * SPL_STR;
    const int bh = blockIdx.x;
    const int b = bh >> 8;
    const int tid = threadIdx.x;  // = w
    const int wrp = tid >> 5;
    const float* xb = x + ((size_t)b * NC * NH + (bh & 255)) * NW;
#pragma unroll 4
    for (int c = 0; c < NC; c++) {
        float v = xb[(size_t)c * (NH * NW) + tid];
        __half hi = __float2half_rn(v);
        __half lo = __float2half_rn(v - __half2float(hi));
        SH[tid * SPL_STR + c] = hi;
        SL[tid * SPL_STR + c] = lo;
#pragma unroll
        for (int off = 16; off; off >>= 1) v += __shfl_down_sync(0xFFFFFFFFu, v, off);
        if ((tid & 31) == 0) psum[c][wrp] = v;
    }
    __syncthreads();
    if (tid < NC) {
        float s = 0.f;
#pragma unroll
        for (int j = 0; j < 8; j++) s += psum[tid][j];
        atomicAdd(&g_pooled[b * NC + tid], s * (1.0f / (NH * NW)));
    }
    unsigned* oh = (unsigned*)(g_xhi + (size_t)bh * NW * NC);
    unsigned* ol = (unsigned*)(g_xlo + (size_t)bh * NW * NC);
    const unsigned* sh32 = (const unsigned*)SH;
    const unsigned* sl32 = (const unsigned*)SL;
#pragma unroll
    for (int i = tid; i < NW * 32; i += 256) {
        int w = i >> 5, c2 = i & 31;
        oh[w * 32 + c2] = sh32[w * 33 + c2];
        ol[w * 32 + c2] = sl32[w * 33 + c2];
    }
}

// ---------------------------------------------------------------------------
// Kernel 2: attention MLP + softmax (re-zeroes g_pooled for graph replay)
// ---------------------------------------------------------------------------
__global__ void att_kernel(const float* __restrict__ fc1,
                           const float* __restrict__ fc2,
                           const float* __restrict__ fc2b) {
    __shared__ float sp[NB * NC];
    __shared__ float sf1[HID * NC];
    __shared__ float sh[NB][HID];
    int t = threadIdx.x;
    for (int i = t; i < NB * NC; i += blockDim.x) sp[i] = g_pooled[i];
    for (int i = t; i < HID * NC; i += blockDim.x) sf1[i] = fc1[i];
    __syncthreads();
    for (int i = t; i < NB * NC; i += blockDim.x) g_pooled[i] = 0.f;
    if (t < NB * HID) {
        int b = t / HID, j = t % HID;
        float s = 0.f;
#pragma unroll
        for (int c = 0; c < NC; c++) s += sp[b * NC + c] * sf1[j * NC + c];
        sh[b][j] = s >= 0.f ? s : SLOPE * s;
    }
    __syncthreads();
    if (t < NB) {
        int b = t;
        float lg[NK];
        float m = -1e30f;
#pragma unroll
        for (int k = 0; k < NK; k++) {
            float s = fc2b[k];
#pragma unroll
            for (int j = 0; j < HID; j++) s += sh[b][j] * fc2[k * HID + j];
            lg[k] = s / TEMP;
            m = fmaxf(m, lg[k]);
        }
        float den = 0.f, e[NK];
#pragma unroll
        for (int k = 0; k < NK; k++) { e[k] = expf(lg[k] - m); den += e[k]; }
        float inv = 1.0f / den;
#pragma unroll
        for (int k = 0; k < NK; k++) g_att[b * NK + k] = e[k] * inv;
    }
}

// ---------------------------------------------------------------------------
// Kernel 3: aggregate weights -> fp16, layout [b][ky][o][kx][c]
// ---------------------------------------------------------------------------
__global__ void agg_kernel(const float* __restrict__ weight,  // [K][O][I][3][3]
                           const float* __restrict__ bias_k) {
    int idx = blockIdx.x * 256 + threadIdx.x;
    const int TOT = NB * 3 * NO * 3 * NC;  // 589824
    if (idx < TOT) {
        int c = idx & 63;
        int t1 = idx >> 6;
        int kx = t1 % 3; t1 /= 3;
        int o = t1 & 63; t1 >>= 6;
        int ky = t1 % 3;
        int b = t1 / 3;
        const int KS = NO * NC * 9;
        int wb = (o * NC + c) * 9 + ky * 3 + kx;
        float s = g_att[b * NK + 0] * weight[wb] +
                  g_att[b * NK + 1] * weight[wb + KS] +
                  g_att[b * NK + 2] * weight[wb + 2 * KS] +
                  g_att[b * NK + 3] * weight[wb + 3 * KS];
        g_awh[idx] = __float2half_rn(s);
    }
    if (idx < NB * NO) {
        int b = idx >> 6, o = idx & 63;
        float s = 0.f;
#pragma unroll
        for (int k = 0; k < NK; k++) s += g_att[b * NK + k] * bias_k[k * NO + o];
        g_aggb[idx] = s;
    }
}

// ---------------------------------------------------------------------------
// Kernel 4: mma.sync fp16 2-term conv, K'=192 per ky. 512 thr, 8m x 2n warps.
// CTA = (b, row-pair, half): 2 rows x 128 px x 64 out.
// X: flat [row][px][c] hi/lo fp16 planes, SW128-swizzled.
// B: fp16 hi only, [o][k'] stride 400 B, DOUBLE buffered, 1 barrier per ky.
// ---------------------------------------------------------------------------
#define XPLANE (4 * 130 * 128)            // 66560 B per plane
#define OFF_B (2 * XPLANE)                // 133120
#define BSTR 400                          // bytes per o-row (192*2 + 16 pad)
#define BPL (64 * BSTR)                   // 25600 B per buffer
#define CONV_SMEM (OFF_B + 2 * BPL)       // 184320 B

__global__ void __launch_bounds__(512, 1)
conv_kernel(float* __restrict__ out) {
    extern __shared__ char smem[];
    const unsigned sb = smem_u32(smem);
    const int tid = threadIdx.x;
    const int lane = tid & 31, wid = tid >> 5;
    const int wm = wid & 7, wn = wid >> 3;   // 8m x 2n
    const int b = blockIdx.y;
    const int y0 = (blockIdx.x >> 1) * 2;
    const int x0 = (blockIdx.x & 1) * 128;

    // ---- stage X (2 planes x 4 rows x 130 px x 128B, swizzled) ----
    {
        const size_t bbase = (size_t)b * NH * NW * NC;
        for (int i = tid; i < 8320; i += 512) {
            int plane = (i >= 4160) ? 1 : 0;
            int q = i - plane * 4160;
            int ch = q & 7;
            int rc = q >> 3;                    // r*130 + cl
            int r = rc / 130, cl = rc - r * 130;
            int gy = y0 - 1 + r, gx = x0 - 1 + cl;
            bool ok = ((unsigned)gy < 256u) && ((unsigned)gx < 256u);
            const __half* base = plane ? g_xlo : g_xhi;
            const void* src = base + bbase +
                              ((size_t)(ok ? (gy * 256 + gx) : 0) * 64) + ch * 8;
            unsigned o = (unsigned)(plane * XPLANE + rc * 128 + ch * 16);
            cp16z(sb + sw128(o), src, ok ? 16 : 0);
        }
    }

    // ---- B staging: 1536 chunks of 16B per ky (fp16 hi only) ----
    const __half* awh = g_awh + (size_t)(b * 3) * (NO * 192);
#define STAGE_B(KY, BUF)                                                         \
    {                                                                            \
        _Pragma("unroll")                                                        \
        for (int j = 0; j < 3; j++) {                                            \
            int q = tid + j * 512;                                               \
            int o = q / 24, ck = q - o * 24;                                     \
            const void* src = awh + ((KY) * NO + o) * 192 + ck * 8;              \
            unsigned dst = sb + OFF_B + (BUF) * BPL + o * BSTR + ck * 16;        \
            cp16(dst, src);                                                      \
        }                                                                        \
        asm volatile("cp.async.commit_group;");                                  \
    }

    STAGE_B(0, 0);  // commits X + B0 together as one group

    float acc[2][4][4];
#pragma unroll
    for (int rw = 0; rw < 2; rw++)
#pragma unroll
        for (int tn = 0; tn < 4; tn++)
#pragma unroll
            for (int r = 0; r < 4; r++) acc[rw][tn][r] = 0.f;

    // A lane addressing (m16 x k16 tile per x4)
    const int apx = wm * 16 + (lane & 15);
    const unsigned aklo = (lane & 16) ? 16u : 0u;
    // B lane addressing (n16 x k16 per x4; two n-groups for n=32)
    const int bq = lane >> 3;
    const int brow = ((bq & 2) << 2) + (lane & 7);
    const unsigned bklo = (unsigned)((bq & 1) * 16);
    const unsigned brbase = (unsigned)((wn * 32 + brow) * BSTR) + bklo;

#pragma unroll 1
    for (int ky = 0; ky < 3; ky++) {
        asm volatile("cp.async.wait_group 0;");
        __syncthreads();  // B(ky) visible everywhere; all warps done with old buffer
        if (ky < 2) STAGE_B(ky + 1, (ky + 1) & 1);  // overlaps with compute(ky)

        const unsigned bbase0 = sb + OFF_B + (unsigned)((ky & 1) * BPL) + brbase;
        const unsigned bbase1 = bbase0 + 16 * BSTR;

#pragma unroll 2
        for (int kc = 0; kc < 12; kc++) {
            unsigned bh0[4], bh1[4];
            ldmatrix_x4(bh0[0], bh0[1], bh0[2], bh0[3], bbase0 + kc * 32);
            ldmatrix_x4(bh1[0], bh1[1], bh1[2], bh1[3], bbase1 + kc * 32);
#pragma unroll
            for (int rw = 0; rw < 2; rw++) {
                unsigned o_ = (unsigned)(((ky + rw) * 130 + apx) * 128 + kc * 32) + aklo;
                unsigned hc[4], lc[4];
                ldmatrix_x4(hc[0], hc[1], hc[2], hc[3], sb + sw128(o_));
                ldmatrix_x4(lc[0], lc[1], lc[2], lc[3], sb + sw128(o_ + XPLANE));
                mma16816(acc[rw][0], hc, bh0[0], bh0[1]);
                mma16816(acc[rw][0], lc, bh0[0], bh0[1]);
                mma16816(acc[rw][1], hc, bh0[2], bh0[3]);
                mma16816(acc[rw][1], lc, bh0[2], bh0[3]);
                mma16816(acc[rw][2], hc, bh1[0], bh1[1]);
                mma16816(acc[rw][2], lc, bh1[0], bh1[1]);
                mma16816(acc[rw][3], hc, bh1[2], bh1[3]);
                mma16816(acc[rw][3], lc, bh1[2], bh1[3]);
            }
        }
    }

    // ---- epilogue: bias + store (2 rows) ----
    const int m0 = x0 + wm * 16 + (lane >> 2);
#pragma unroll
    for (int rw = 0; rw < 2; rw++) {
        const int y = y0 + rw;
#pragma unroll
        for (int tn = 0; tn < 4; tn++) {
            int n0 = wn * 32 + tn * 8 + (lane & 3) * 2;
            float bv0 = g_aggb[b * NO + n0];
            float bv1 = g_aggb[b * NO + n0 + 1];
            size_t p0 = ((size_t)(b * NO + n0) * NH + y) * NW;
            size_t p1 = ((size_t)(b * NO + n0 + 1) * NH + y) * NW;
            out[p0 + m0] = acc[rw][tn][0] + bv0;
            out[p1 + m0] = acc[rw][tn][1] + bv1;
            out[p0 + m0 + 8] = acc[rw][tn][2] + bv0;
            out[p1 + m0 + 8] = acc[rw][tn][3] + bv1;
        }
    }
#undef STAGE_B
}

// ---------------------------------------------------------------------------
extern "C" void kernel_launch(void* const* d_in, const int* in_sizes, int n_in,
                              void* d_out, int out_size) {
    const float* x      = (const float*)d_in[0];
    const float* fc1_w  = (const float*)d_in[1];
    const float* fc2_w  = (const float*)d_in[2];
    const float* fc2_b  = (const float*)d_in[3];
    const float* weight = (const float*)d_in[4];
    const float* bias_k = (const float*)d_in[5];
    float* out = (float*)d_out;

    cudaFuncSetAttribute(split_kernel, cudaFuncAttributeMaxDynamicSharedMemorySize,
                         SPL_SMEM);
    cudaFuncSetAttribute(conv_kernel, cudaFuncAttributeMaxDynamicSharedMemorySize,
                         CONV_SMEM);

    split_kernel<<<NB * NH, 256, SPL_SMEM>>>(x);
    att_kernel<<<1, 288>>>(fc1_w, fc2_w, fc2_b);
    agg_kernel<<<(NB * 3 * NO * 3 * NC + 255) / 256, 256>>>(weight, bias_k);
    conv_kernel<<<dim3(NH, NB), 512, CONV_SMEM>>>(out);
}

// round 13
// speedup vs baseline: 1.9653x; 1.0235x over previous
#include <cuda_runtime.h>
#include <cuda_fp16.h>
#include <cstdint>

#define NB 16
#define NC 64
#define NH 256
#define NW 256
#define NK 4
#define NO 64
#define HID 17
#define TEMP 34.0f
#define SLOPE 0.2f

// Scratch (device globals; allocation-free rule)
__device__ float g_pooled[NB * NC];   // zero-init; re-zeroed by att_kernel each call
__device__ float g_att[NB * NK];
// Aggregated fp16 weights, layout [b][ky][o][kx][c]  (k' = kx*64+c contiguous 192)
__device__ __align__(16) __half g_awh[NB * 3 * NO * 3 * NC];
__device__ float g_aggb[NB * NO];
// Pre-split, transposed input: [b][h][w][c], fp16 hi/lo planes
__device__ __align__(16) __half g_xhi[(size_t)NB * NH * NW * NC];
__device__ __align__(16) __half g_xlo[(size_t)NB * NH * NW * NC];

__device__ __forceinline__ unsigned smem_u32(const void* p) {
    unsigned a;
    asm("{ .reg .u64 t; cvta.to.shared.u64 t, %1; cvt.u32.u64 %0, t; }" : "=r"(a) : "l"(p));
    return a;
}
__device__ __forceinline__ unsigned sw128(unsigned o) { return o ^ ((o >> 3) & 0x70); }
__device__ __forceinline__ void ldmatrix_x4(unsigned& r0, unsigned& r1, unsigned& r2,
                                            unsigned& r3, unsigned addr) {
    asm volatile("ldmatrix.sync.aligned.m8n8.x4.shared.b16 {%0,%1,%2,%3}, [%4];"
                 : "=r"(r0), "=r"(r1), "=r"(r2), "=r"(r3) : "r"(addr));
}
__device__ __forceinline__ void mma16816(float* d, const unsigned* a, unsigned b0,
                                         unsigned b1) {
    asm volatile(
        "mma.sync.aligned.m16n8k16.row.col.f32.f16.f16.f32 "
        "{%0,%1,%2,%3}, {%4,%5,%6,%7}, {%8,%9}, {%0,%1,%2,%3};"
        : "+f"(d[0]), "+f"(d[1]), "+f"(d[2]), "+f"(d[3])
        : "r"(a[0]), "r"(a[1]), "r"(a[2]), "r"(a[3]), "r"(b0), "r"(b1));
}
__device__ __forceinline__ void cp16(unsigned dst, const void* src) {
    asm volatile("cp.async.ca.shared.global [%0], [%1], 16;" :: "r"(dst), "l"(src));
}
__device__ __forceinline__ void cp16z(unsigned dst, const void* src, int sz) {
    asm volatile("cp.async.ca.shared.global [%0], [%1], 16, %2;"
                 :: "r"(dst), "l"(src), "r"(sz));
}

// ---------------------------------------------------------------------------
// Kernel 0: split x into fp16 hi/lo planes [b][h][w][c]  +  fused avg-pool.
// ---------------------------------------------------------------------------
#define SPL_STR 66
#define SPL_SMEM (2 * NW * SPL_STR * 2)  // 67584 B

__global__ void __launch_bounds__(256)
split_kernel(const float* __restrict__ x) {
    extern __shared__ __half sp[];
    __shared__ float psum[NC][8];
    __half* SH = sp;
    __half* SL = sp + NW * SPL_STR;
    const int bh = blockIdx.x;
    const int b = bh >> 8;
    const int tid = threadIdx.x;  // = w
    const int wrp = tid >> 5;
    const float* xb = x + ((size_t)b * NC * NH + (bh & 255)) * NW;
#pragma unroll 4
    for (int c = 0; c < NC; c++) {
        float v = xb[(size_t)c * (NH * NW) + tid];
        __half hi = __float2half_rn(v);
        __half lo = __float2half_rn(v - __half2float(hi));
        SH[tid * SPL_STR + c] = hi;
        SL[tid * SPL_STR + c] = lo;
#pragma unroll
        for (int off = 16; off; off >>= 1) v += __shfl_down_sync(0xFFFFFFFFu, v, off);
        if ((tid & 31) == 0) psum[c][wrp] = v;
    }
    __syncthreads();
    if (tid < NC) {
        float s = 0.f;
#pragma unroll
        for (int j = 0; j < 8; j++) s += psum[tid][j];
        atomicAdd(&g_pooled[b * NC + tid], s * (1.0f / (NH * NW)));
    }
    unsigned* oh = (unsigned*)(g_xhi + (size_t)bh * NW * NC);
    unsigned* ol = (unsigned*)(g_xlo + (size_t)bh * NW * NC);
    const unsigned* sh32 = (const unsigned*)SH;
    const unsigned* sl32 = (const unsigned*)SL;
#pragma unroll
    for (int i = tid; i < NW * 32; i += 256) {
        int w = i >> 5, c2 = i & 31;
        oh[w * 32 + c2] = sh32[w * 33 + c2];
        ol[w * 32 + c2] = sl32[w * 33 + c2];
    }
}

// ---------------------------------------------------------------------------
// Kernel 2: attention MLP + softmax (re-zeroes g_pooled for graph replay)
// ---------------------------------------------------------------------------
__global__ void att_kernel(const float* __restrict__ fc1,
                           const float* __restrict__ fc2,
                           const float* __restrict__ fc2b) {
    __shared__ float sp[NB * NC];
    __shared__ float sf1[HID * NC];
    __shared__ float sh[NB][HID];
    int t = threadIdx.x;
    for (int i = t; i < NB * NC; i += blockDim.x) sp[i] = g_pooled[i];
    for (int i = t; i < HID * NC; i += blockDim.x) sf1[i] = fc1[i];
    __syncthreads();
    for (int i = t; i < NB * NC; i += blockDim.x) g_pooled[i] = 0.f;
    if (t < NB * HID) {
        int b = t / HID, j = t % HID;
        float s = 0.f;
#pragma unroll
        for (int c = 0; c < NC; c++) s += sp[b * NC + c] * sf1[j * NC + c];
        sh[b][j] = s >= 0.f ? s : SLOPE * s;
    }
    __syncthreads();
    if (t < NB) {
        int b = t;
        float lg[NK];
        float m = -1e30f;
#pragma unroll
        for (int k = 0; k < NK; k++) {
            float s = fc2b[k];
#pragma unroll
            for (int j = 0; j < HID; j++) s += sh[b][j] * fc2[k * HID + j];
            lg[k] = s / TEMP;
            m = fmaxf(m, lg[k]);
        }
        float den = 0.f, e[NK];
#pragma unroll
        for (int k = 0; k < NK; k++) { e[k] = expf(lg[k] - m); den += e[k]; }
        float inv = 1.0f / den;
#pragma unroll
        for (int k = 0; k < NK; k++) g_att[b * NK + k] = e[k] * inv;
    }
}

// ---------------------------------------------------------------------------
// Kernel 3: aggregate weights -> fp16, layout [b][ky][o][kx][c]
// ---------------------------------------------------------------------------
__global__ void agg_kernel(const float* __restrict__ weight,  // [K][O][I][3][3]
                           const float* __restrict__ bias_k) {
    int idx = blockIdx.x * 256 + threadIdx.x;
    const int TOT = NB * 3 * NO * 3 * NC;  // 589824
    if (idx < TOT) {
        int c = idx & 63;
        int t1 = idx >> 6;
        int kx = t1 % 3; t1 /= 3;
        int o = t1 & 63; t1 >>= 6;
        int ky = t1 % 3;
        int b = t1 / 3;
        const int KS = NO * NC * 9;
        int wb = (o * NC + c) * 9 + ky * 3 + kx;
        float s = g_att[b * NK + 0] * weight[wb] +
                  g_att[b * NK + 1] * weight[wb + KS] +
                  g_att[b * NK + 2] * weight[wb + 2 * KS] +
                  g_att[b * NK + 3] * weight[wb + 3 * KS];
        g_awh[idx] = __float2half_rn(s);
    }
    if (idx < NB * NO) {
        int b = idx >> 6, o = idx & 63;
        float s = 0.f;
#pragma unroll
        for (int k = 0; k < NK; k++) s += g_att[b * NK + k] * bias_k[k * NO + o];
        g_aggb[idx] = s;
    }
}

// ---------------------------------------------------------------------------
// Kernel 4: mma.sync fp16 2-term conv. 512 thr, warp grid 8m x 2n.
// CTA = (b, row-pair, half): 2 rows x 128 px x 64 out.
// ALL 3 ky B planes resident; ONE cp.async wait + ONE barrier total.
// kc-outer loop: B frags cached in regs (24), each A row loaded exactly once.
// ---------------------------------------------------------------------------
#define XPLANE (4 * 130 * 128)            // 66560 B per plane
#define OFF_B (2 * XPLANE)                // 133120
#define BSTR 400                          // bytes per o-row (192*2 + 16 pad)
#define BPL (64 * BSTR)                   // 25600 B per ky plane
#define CONV_SMEM (OFF_B + 3 * BPL)       // 209920 B

__global__ void __launch_bounds__(512, 1)
conv_kernel(float* __restrict__ out) {
    extern __shared__ char smem[];
    const unsigned sb = smem_u32(smem);
    const int tid = threadIdx.x;
    const int lane = tid & 31, wid = tid >> 5;
    const int wm = wid & 7, wn = wid >> 3;   // 8m x 2n
    const int b = blockIdx.y;
    const int y0 = (blockIdx.x >> 1) * 2;
    const int x0 = (blockIdx.x & 1) * 128;

    // ---- stage X (2 planes x 4 rows x 130 px x 128B, swizzled) ----
    {
        const size_t bbase = (size_t)b * NH * NW * NC;
        for (int i = tid; i < 8320; i += 512) {
            int plane = (i >= 4160) ? 1 : 0;
            int q = i - plane * 4160;
            int ch = q & 7;
            int rc = q >> 3;                    // r*130 + cl
            int r = rc / 130, cl = rc - r * 130;
            int gy = y0 - 1 + r, gx = x0 - 1 + cl;
            bool ok = ((unsigned)gy < 256u) && ((unsigned)gx < 256u);
            const __half* base = plane ? g_xlo : g_xhi;
            const void* src = base + bbase +
                              ((size_t)(ok ? (gy * 256 + gx) : 0) * 64) + ch * 8;
            unsigned o = (unsigned)(plane * XPLANE + rc * 128 + ch * 16);
            cp16z(sb + sw128(o), src, ok ? 16 : 0);
        }
    }
    // ---- stage B: all 3 ky planes (4608 chunks of 16B) ----
    {
        const __half* awh = g_awh + (size_t)(b * 3) * (NO * 192);
#pragma unroll
        for (int j = 0; j < 9; j++) {
            int q = tid + j * 512;
            int o = q / 24, ck = q - o * 24;   // o in [0,192): ky*64 + och
            const void* src = awh + o * 192 + ck * 8;
            unsigned dst = sb + OFF_B + o * BSTR + ck * 16;  // 3 planes contiguous
            cp16(dst, src);
        }
        asm volatile("cp.async.commit_group;");
    }
    asm volatile("cp.async.wait_group 0;");
    __syncthreads();  // the only barrier in the kernel

    float acc[2][4][4];
#pragma unroll
    for (int rw = 0; rw < 2; rw++)
#pragma unroll
        for (int tn = 0; tn < 4; tn++)
#pragma unroll
            for (int r = 0; r < 4; r++) acc[rw][tn][r] = 0.f;

    // A lane addressing (m16 x k16 tile per x4)
    const int apx = wm * 16 + (lane & 15);
    const unsigned aklo = (lane & 16) ? 16u : 0u;
    // B lane addressing (n16 x k16 per x4; two n-groups for n=32)
    const int bq = lane >> 3;
    const int brow = ((bq & 2) << 2) + (lane & 7);
    const unsigned bklo = (unsigned)((bq & 1) * 16);
    const unsigned brbase = sb + OFF_B + (unsigned)((wn * 32 + brow) * BSTR) + bklo;

#pragma unroll 2
    for (int kc = 0; kc < 12; kc++) {
        // Load all B fragments for this kc: 3 ky x 2 n-groups
        unsigned B0[3][4], B1[3][4];
#pragma unroll
        for (int ky = 0; ky < 3; ky++) {
            unsigned b0 = brbase + (unsigned)(ky * BPL) + kc * 32;
            ldmatrix_x4(B0[ky][0], B0[ky][1], B0[ky][2], B0[ky][3], b0);
            ldmatrix_x4(B1[ky][0], B1[ky][1], B1[ky][2], B1[ky][3], b0 + 16 * BSTR);
        }
        // Each x-row loaded once; contributes to out rows rw = r - ky
#pragma unroll
        for (int r = 0; r < 4; r++) {
            unsigned o_ = (unsigned)((r * 130 + apx) * 128 + kc * 32) + aklo;
            unsigned hc[4], lc[4];
            ldmatrix_x4(hc[0], hc[1], hc[2], hc[3], sb + sw128(o_));
            ldmatrix_x4(lc[0], lc[1], lc[2], lc[3], sb + sw128(o_ + XPLANE));
#pragma unroll
            for (int ky = 0; ky < 3; ky++) {
                const int rw = r - ky;
                if (rw == 0 || rw == 1) {
                    mma16816(acc[rw][0], hc, B0[ky][0], B0[ky][1]);
                    mma16816(acc[rw][0], lc, B0[ky][0], B0[ky][1]);
                    mma16816(acc[rw][1], hc, B0[ky][2], B0[ky][3]);
                    mma16816(acc[rw][1], lc, B0[ky][2], B0[ky][3]);
                    mma16816(acc[rw][2], hc, B1[ky][0], B1[ky][1]);
                    mma16816(acc[rw][2], lc, B1[ky][0], B1[ky][1]);
                    mma16816(acc[rw][3], hc, B1[ky][2], B1[ky][3]);
                    mma16816(acc[rw][3], lc, B1[ky][2], B1[ky][3]);
                }
            }
        }
    }

    // ---- epilogue: bias + store (2 rows) ----
    const int m0 = x0 + wm * 16 + (lane >> 2);
#pragma unroll
    for (int rw = 0; rw < 2; rw++) {
        const int y = y0 + rw;
#pragma unroll
        for (int tn = 0; tn < 4; tn++) {
            int n0 = wn * 32 + tn * 8 + (lane & 3) * 2;
            float bv0 = g_aggb[b * NO + n0];
            float bv1 = g_aggb[b * NO + n0 + 1];
            size_t p0 = ((size_t)(b * NO + n0) * NH + y) * NW;
            size_t p1 = ((size_t)(b * NO + n0 + 1) * NH + y) * NW;
            out[p0 + m0] = acc[rw][tn][0] + bv0;
            out[p1 + m0] = acc[rw][tn][1] + bv1;
            out[p0 + m0 + 8] = acc[rw][tn][2] + bv0;
            out[p1 + m0 + 8] = acc[rw][tn][3] + bv1;
        }
    }
}

// ---------------------------------------------------------------------------
extern "C" void kernel_launch(void* const* d_in, const int* in_sizes, int n_in,
                              void* d_out, int out_size) {
    const float* x      = (const float*)d_in[0];
    const float* fc1_w  = (const float*)d_in[1];
    const float* fc2_w  = (const float*)d_in[2];
    const float* fc2_b  = (const float*)d_in[3];
    const float* weight = (const float*)d_in[4];
    const float* bias_k = (const float*)d_in[5];
    float* out = (float*)d_out;

    cudaFuncSetAttribute(split_kernel, cudaFuncAttributeMaxDynamicSharedMemorySize,
                         SPL_SMEM);
    cudaFuncSetAttribute(conv_kernel, cudaFuncAttributeMaxDynamicSharedMemorySize,
                         CONV_SMEM);

    split_kernel<<<NB * NH, 256, SPL_SMEM>>>(x);
    att_kernel<<<1, 288>>>(fc1_w, fc2_w, fc2_b);
    agg_kernel<<<(NB * 3 * NO * 3 * NC + 255) / 256, 256>>>(weight, bias_k);
    conv_kernel<<<dim3(NH, NB), 512, CONV_SMEM>>>(out);
}

// round 14
// speedup vs baseline: 3.4075x; 1.7338x over previous
#include <cuda_runtime.h>
#include <cuda_fp16.h>
#include <cstdint>

#define NB 16
#define NC 64
#define NH 256
#define NW 256
#define NK 4
#define NO 64
#define HID 17
#define TEMP 34.0f
#define SLOPE 0.2f

// Scratch (device globals; allocation-free rule)
__device__ float g_pooled[NB * NC];   // zero-init; re-zeroed by att_kernel each call
__device__ float g_att[NB * NK];
// Aggregated fp16 weights, layout [b][ky][o][kx][c]  (k' = kx*64+c contiguous 192)
__device__ __align__(16) __half g_awh[NB * 3 * NO * 3 * NC];
__device__ float g_aggb[NB * NO];
// fp16 transposed input: [b][h][w][c]
__device__ __align__(16) __half g_xh[(size_t)NB * NH * NW * NC];

__device__ __forceinline__ unsigned smem_u32(const void* p) {
    unsigned a;
    asm("{ .reg .u64 t; cvta.to.shared.u64 t, %1; cvt.u32.u64 %0, t; }" : "=r"(a) : "l"(p));
    return a;
}
__device__ __forceinline__ unsigned sw128(unsigned o) { return o ^ ((o >> 3) & 0x70); }
__device__ __forceinline__ void ldmatrix_x4(unsigned& r0, unsigned& r1, unsigned& r2,
                                            unsigned& r3, unsigned addr) {
    asm volatile("ldmatrix.sync.aligned.m8n8.x4.shared.b16 {%0,%1,%2,%3}, [%4];"
                 : "=r"(r0), "=r"(r1), "=r"(r2), "=r"(r3) : "r"(addr));
}
__device__ __forceinline__ void mma16816(float* d, const unsigned* a, unsigned b0,
                                         unsigned b1) {
    asm volatile(
        "mma.sync.aligned.m16n8k16.row.col.f32.f16.f16.f32 "
        "{%0,%1,%2,%3}, {%4,%5,%6,%7}, {%8,%9}, {%0,%1,%2,%3};"
        : "+f"(d[0]), "+f"(d[1]), "+f"(d[2]), "+f"(d[3])
        : "r"(a[0]), "r"(a[1]), "r"(a[2]), "r"(a[3]), "r"(b0), "r"(b1));
}
__device__ __forceinline__ void cp16(unsigned dst, const void* src) {
    asm volatile("cp.async.ca.shared.global [%0], [%1], 16;" :: "r"(dst), "l"(src));
}
__device__ __forceinline__ void cp16z(unsigned dst, const void* src, int sz) {
    asm volatile("cp.async.ca.shared.global [%0], [%1], 16, %2;"
                 :: "r"(dst), "l"(src), "r"(sz));
}

// ---------------------------------------------------------------------------
// Kernel 0: x -> fp16 [b][h][w][c] transpose + fused avg-pool.
// ---------------------------------------------------------------------------
#define SPL_STR 66
#define SPL_SMEM (NW * SPL_STR * 2)  // 33792 B

__global__ void __launch_bounds__(256)
split_kernel(const float* __restrict__ x) {
    extern __shared__ __half sp[];
    __shared__ float psum[NC][8];
    const int bh = blockIdx.x;
    const int b = bh >> 8;
    const int tid = threadIdx.x;  // = w
    const int wrp = tid >> 5;
    const float* xb = x + ((size_t)b * NC * NH + (bh & 255)) * NW;
#pragma unroll 4
    for (int c = 0; c < NC; c++) {
        float v = xb[(size_t)c * (NH * NW) + tid];
        sp[tid * SPL_STR + c] = __float2half_rn(v);
#pragma unroll
        for (int off = 16; off; off >>= 1) v += __shfl_down_sync(0xFFFFFFFFu, v, off);
        if ((tid & 31) == 0) psum[c][wrp] = v;
    }
    __syncthreads();
    if (tid < NC) {
        float s = 0.f;
#pragma unroll
        for (int j = 0; j < 8; j++) s += psum[tid][j];
        atomicAdd(&g_pooled[b * NC + tid], s * (1.0f / (NH * NW)));
    }
    unsigned* oh = (unsigned*)(g_xh + (size_t)bh * NW * NC);
    const unsigned* sh32 = (const unsigned*)sp;
#pragma unroll
    for (int i = tid; i < NW * 32; i += 256) {
        int w = i >> 5, c2 = i & 31;
        oh[w * 32 + c2] = sh32[w * 33 + c2];
    }
}

// ---------------------------------------------------------------------------
// Kernel 2: attention MLP + softmax (re-zeroes g_pooled for graph replay)
// ---------------------------------------------------------------------------
__global__ void att_kernel(const float* __restrict__ fc1,
                           const float* __restrict__ fc2,
                           const float* __restrict__ fc2b) {
    __shared__ float sp[NB * NC];
    __shared__ float sf1[HID * NC];
    __shared__ float sh[NB][HID];
    int t = threadIdx.x;
    for (int i = t; i < NB * NC; i += blockDim.x) sp[i] = g_pooled[i];
    for (int i = t; i < HID * NC; i += blockDim.x) sf1[i] = fc1[i];
    __syncthreads();
    for (int i = t; i < NB * NC; i += blockDim.x) g_pooled[i] = 0.f;
    if (t < NB * HID) {
        int b = t / HID, j = t % HID;
        float s = 0.f;
#pragma unroll
        for (int c = 0; c < NC; c++) s += sp[b * NC + c] * sf1[j * NC + c];
        sh[b][j] = s >= 0.f ? s : SLOPE * s;
    }
    __syncthreads();
    if (t < NB) {
        int b = t;
        float lg[NK];
        float m = -1e30f;
#pragma unroll
        for (int k = 0; k < NK; k++) {
            float s = fc2b[k];
#pragma unroll
            for (int j = 0; j < HID; j++) s += sh[b][j] * fc2[k * HID + j];
            lg[k] = s / TEMP;
            m = fmaxf(m, lg[k]);
        }
        float den = 0.f, e[NK];
#pragma unroll
        for (int k = 0; k < NK; k++) { e[k] = expf(lg[k] - m); den += e[k]; }
        float inv = 1.0f / den;
#pragma unroll
        for (int k = 0; k < NK; k++) g_att[b * NK + k] = e[k] * inv;
    }
}

// ---------------------------------------------------------------------------
// Kernel 3: aggregate weights -> fp16, layout [b][ky][o][kx][c]
// ---------------------------------------------------------------------------
__global__ void agg_kernel(const float* __restrict__ weight,  // [K][O][I][3][3]
                           const float* __restrict__ bias_k) {
    int idx = blockIdx.x * 256 + threadIdx.x;
    const int TOT = NB * 3 * NO * 3 * NC;  // 589824
    if (idx < TOT) {
        int c = idx & 63;
        int t1 = idx >> 6;
        int kx = t1 % 3; t1 /= 3;
        int o = t1 & 63; t1 >>= 6;
        int ky = t1 % 3;
        int b = t1 / 3;
        const int KS = NO * NC * 9;
        int wb = (o * NC + c) * 9 + ky * 3 + kx;
        float s = g_att[b * NK + 0] * weight[wb] +
                  g_att[b * NK + 1] * weight[wb + KS] +
                  g_att[b * NK + 2] * weight[wb + 2 * KS] +
                  g_att[b * NK + 3] * weight[wb + 3 * KS];
        g_awh[idx] = __float2half_rn(s);
    }
    if (idx < NB * NO) {
        int b = idx >> 6, o = idx & 63;
        float s = 0.f;
#pragma unroll
        for (int k = 0; k < NK; k++) s += g_att[b * NK + k] * bias_k[k * NO + o];
        g_aggb[idx] = s;
    }
}

// ---------------------------------------------------------------------------
// Kernel 4: mma.sync fp16 single-term conv. 512 thr, warp grid 8m x 2n.
// CTA = (b, row-pair, half): 2 rows x 128 px x 64 out.
// X single fp16 plane (SW128); all 3 ky B planes resident; ONE barrier.
// ---------------------------------------------------------------------------
#define XPLANE (4 * 130 * 128)            // 66560 B
#define OFF_B XPLANE
#define BSTR 400                          // bytes per o-row (192*2 + 16 pad)
#define BPL (64 * BSTR)                   // 25600 B per ky plane
#define CONV_SMEM (OFF_B + 3 * BPL)       // 143360 B

__global__ void __launch_bounds__(512, 1)
conv_kernel(float* __restrict__ out) {
    extern __shared__ char smem[];
    const unsigned sb = smem_u32(smem);
    const int tid = threadIdx.x;
    const int lane = tid & 31, wid = tid >> 5;
    const int wm = wid & 7, wn = wid >> 3;   // 8m x 2n
    const int b = blockIdx.y;
    const int y0 = (blockIdx.x >> 1) * 2;
    const int x0 = (blockIdx.x & 1) * 128;

    // ---- stage X (4 rows x 130 px x 128B, swizzled) ----
    {
        const size_t bbase = (size_t)b * NH * NW * NC;
        for (int i = tid; i < 4160; i += 512) {
            int ch = i & 7;
            int rc = i >> 3;                    // r*130 + cl
            int r = rc / 130, cl = rc - r * 130;
            int gy = y0 - 1 + r, gx = x0 - 1 + cl;
            bool ok = ((unsigned)gy < 256u) && ((unsigned)gx < 256u);
            const void* src = g_xh + bbase +
                              ((size_t)(ok ? (gy * 256 + gx) : 0) * 64) + ch * 8;
            unsigned o = (unsigned)(rc * 128 + ch * 16);
            cp16z(sb + sw128(o), src, ok ? 16 : 0);
        }
    }
    // ---- stage B: all 3 ky planes (4608 chunks of 16B) ----
    {
        const __half* awh = g_awh + (size_t)(b * 3) * (NO * 192);
#pragma unroll
        for (int j = 0; j < 9; j++) {
            int q = tid + j * 512;
            int o = q / 24, ck = q - o * 24;   // o in [0,192): ky*64 + och
            const void* src = awh + o * 192 + ck * 8;
            unsigned dst = sb + OFF_B + o * BSTR + ck * 16;
            cp16(dst, src);
        }
        asm volatile("cp.async.commit_group;");
    }
    asm volatile("cp.async.wait_group 0;");
    __syncthreads();  // the only barrier in the kernel

    float acc[2][4][4];
#pragma unroll
    for (int rw = 0; rw < 2; rw++)
#pragma unroll
        for (int tn = 0; tn < 4; tn++)
#pragma unroll
            for (int r = 0; r < 4; r++) acc[rw][tn][r] = 0.f;

    // A lane addressing (m16 x k16 tile per x4)
    const int apx = wm * 16 + (lane & 15);
    const unsigned aklo = (lane & 16) ? 16u : 0u;
    // B lane addressing (n16 x k16 per x4; two n-groups for n=32)
    const int bq = lane >> 3;
    const int brow = ((bq & 2) << 2) + (lane & 7);
    const unsigned bklo = (unsigned)((bq & 1) * 16);
    const unsigned brbase = sb + OFF_B + (unsigned)((wn * 32 + brow) * BSTR) + bklo;

#pragma unroll 2
    for (int kc = 0; kc < 12; kc++) {
        // Load all B fragments for this kc: 3 ky x 2 n-groups
        unsigned B0[3][4], B1[3][4];
#pragma unroll
        for (int ky = 0; ky < 3; ky++) {
            unsigned b0 = brbase + (unsigned)(ky * BPL) + kc * 32;
            ldmatrix_x4(B0[ky][0], B0[ky][1], B0[ky][2], B0[ky][3], b0);
            ldmatrix_x4(B1[ky][0], B1[ky][1], B1[ky][2], B1[ky][3], b0 + 16 * BSTR);
        }
        // Each x-row loaded once; contributes to out rows rw = r - ky
#pragma unroll
        for (int r = 0; r < 4; r++) {
            unsigned o_ = (unsigned)((r * 130 + apx) * 128 + kc * 32) + aklo;
            unsigned hc[4];
            ldmatrix_x4(hc[0], hc[1], hc[2], hc[3], sb + sw128(o_));
#pragma unroll
            for (int ky = 0; ky < 3; ky++) {
                const int rw = r - ky;
                if (rw == 0 || rw == 1) {
                    mma16816(acc[rw][0], hc, B0[ky][0], B0[ky][1]);
                    mma16816(acc[rw][1], hc, B0[ky][2], B0[ky][3]);
                    mma16816(acc[rw][2], hc, B1[ky][0], B1[ky][1]);
                    mma16816(acc[rw][3], hc, B1[ky][2], B1[ky][3]);
                }
            }
        }
    }

    // ---- epilogue: bias + store (2 rows) ----
    const int m0 = x0 + wm * 16 + (lane >> 2);
#pragma unroll
    for (int rw = 0; rw < 2; rw++) {
        const int y = y0 + rw;
#pragma unroll
        for (int tn = 0; tn < 4; tn++) {
            int n0 = wn * 32 + tn * 8 + (lane & 3) * 2;
            float bv0 = g_aggb[b * NO + n0];
            float bv1 = g_aggb[b * NO + n0 + 1];
            size_t p0 = ((size_t)(b * NO + n0) * NH + y) * NW;
            size_t p1 = ((size_t)(b * NO + n0 + 1) * NH + y) * NW;
            out[p0 + m0] = acc[rw][tn][0] + bv0;
            out[p1 + m0] = acc[rw][tn][1] + bv1;
            out[p0 + m0 + 8] = acc[rw][tn][2] + bv0;
            out[p1 + m0 + 8] = acc[rw][tn][3] + bv1;
        }
    }
}

// ---------------------------------------------------------------------------
extern "C" void kernel_launch(void* const* d_in, const int* in_sizes, int n_in,
                              void* d_out, int out_size) {
    const float* x      = (const float*)d_in[0];
    const float* fc1_w  = (const float*)d_in[1];
    const float* fc2_w  = (const float*)d_in[2];
    const float* fc2_b  = (const float*)d_in[3];
    const float* weight = (const float*)d_in[4];
    const float* bias_k = (const float*)d_in[5];
    float* out = (float*)d_out;

    cudaFuncSetAttribute(split_kernel, cudaFuncAttributeMaxDynamicSharedMemorySize,
                         SPL_SMEM);
    cudaFuncSetAttribute(conv_kernel, cudaFuncAttributeMaxDynamicSharedMemorySize,
                         CONV_SMEM);

    split_kernel<<<NB * NH, 256, SPL_SMEM>>>(x);
    att_kernel<<<1, 288>>>(fc1_w, fc2_w, fc2_b);
    agg_kernel<<<(NB * 3 * NO * 3 * NC + 255) / 256, 256>>>(weight, bias_k);
    conv_kernel<<<dim3(NH, NB), 512, CONV_SMEM>>>(out);
}

// round 15
// speedup vs baseline: 3.5042x; 1.0284x over previous
#include <cuda_runtime.h>
#include <cuda_fp16.h>
#include <cstdint>

#define NB 16
#define NC 64
#define NH 256
#define NW 256
#define NK 4
#define NO 64
#define HID 17
#define TEMP 34.0f
#define SLOPE 0.2f

// Scratch (device globals; allocation-free rule)
__device__ float g_pooled[NB * NC];   // zero-init; re-zeroed by att_kernel each call
__device__ float g_att[NB * NK];
// Aggregated fp16 weights, layout [b][ky][o][kx][c]  (k' = kx*64+c contiguous 192)
__device__ __align__(16) __half g_awh[NB * 3 * NO * 3 * NC];
__device__ float g_aggb[NB * NO];
// fp16 transposed input: [b][h][w][c]
__device__ __align__(16) __half g_xh[(size_t)NB * NH * NW * NC];

__device__ __forceinline__ unsigned smem_u32(const void* p) {
    unsigned a;
    asm("{ .reg .u64 t; cvta.to.shared.u64 t, %1; cvt.u32.u64 %0, t; }" : "=r"(a) : "l"(p));
    return a;
}
__device__ __forceinline__ unsigned sw128(unsigned o) { return o ^ ((o >> 3) & 0x70); }
__device__ __forceinline__ void ldmatrix_x4(unsigned& r0, unsigned& r1, unsigned& r2,
                                            unsigned& r3, unsigned addr) {
    asm volatile("ldmatrix.sync.aligned.m8n8.x4.shared.b16 {%0,%1,%2,%3}, [%4];"
                 : "=r"(r0), "=r"(r1), "=r"(r2), "=r"(r3) : "r"(addr));
}
__device__ __forceinline__ void mma16816(float* d, const unsigned* a, unsigned b0,
                                         unsigned b1) {
    asm volatile(
        "mma.sync.aligned.m16n8k16.row.col.f32.f16.f16.f32 "
        "{%0,%1,%2,%3}, {%4,%5,%6,%7}, {%8,%9}, {%0,%1,%2,%3};"
        : "+f"(d[0]), "+f"(d[1]), "+f"(d[2]), "+f"(d[3])
        : "r"(a[0]), "r"(a[1]), "r"(a[2]), "r"(a[3]), "r"(b0), "r"(b1));
}
__device__ __forceinline__ void cp16(unsigned dst, const void* src) {
    asm volatile("cp.async.ca.shared.global [%0], [%1], 16;" :: "r"(dst), "l"(src));
}
__device__ __forceinline__ void cp16z(unsigned dst, const void* src, int sz) {
    asm volatile("cp.async.ca.shared.global [%0], [%1], 16, %2;"
                 :: "r"(dst), "l"(src), "r"(sz));
}

// ---------------------------------------------------------------------------
// Kernel 0: x -> fp16 [b][h][w][c] transpose + fused avg-pool.
// ---------------------------------------------------------------------------
#define SPL_STR 66
#define SPL_SMEM (NW * SPL_STR * 2)  // 33792 B

__global__ void __launch_bounds__(256)
split_kernel(const float* __restrict__ x) {
    extern __shared__ __half sp[];
    __shared__ float psum[NC][8];
    const int bh = blockIdx.x;
    const int b = bh >> 8;
    const int tid = threadIdx.x;  // = w
    const int wrp = tid >> 5;
    const float* xb = x + ((size_t)b * NC * NH + (bh & 255)) * NW;
#pragma unroll 4
    for (int c = 0; c < NC; c++) {
        float v = xb[(size_t)c * (NH * NW) + tid];
        sp[tid * SPL_STR + c] = __float2half_rn(v);
#pragma unroll
        for (int off = 16; off; off >>= 1) v += __shfl_down_sync(0xFFFFFFFFu, v, off);
        if ((tid & 31) == 0) psum[c][wrp] = v;
    }
    __syncthreads();
    if (tid < NC) {
        float s = 0.f;
#pragma unroll
        for (int j = 0; j < 8; j++) s += psum[tid][j];
        atomicAdd(&g_pooled[b * NC + tid], s * (1.0f / (NH * NW)));
    }
    unsigned* oh = (unsigned*)(g_xh + (size_t)bh * NW * NC);
    const unsigned* sh32 = (const unsigned*)sp;
#pragma unroll
    for (int i = tid; i < NW * 32; i += 256) {
        int w = i >> 5, c2 = i & 31;
        oh[w * 32 + c2] = sh32[w * 33 + c2];
    }
}

// ---------------------------------------------------------------------------
// Kernel 2: attention MLP + softmax (re-zeroes g_pooled for graph replay)
// ---------------------------------------------------------------------------
__global__ void att_kernel(const float* __restrict__ fc1,
                           const float* __restrict__ fc2,
                           const float* __restrict__ fc2b) {
    __shared__ float sp[NB * NC];
    __shared__ float sf1[HID * NC];
    __shared__ float sh[NB][HID];
    int t = threadIdx.x;
    for (int i = t; i < NB * NC; i += blockDim.x) sp[i] = g_pooled[i];
    for (int i = t; i < HID * NC; i += blockDim.x) sf1[i] = fc1[i];
    __syncthreads();
    for (int i = t; i < NB * NC; i += blockDim.x) g_pooled[i] = 0.f;
    if (t < NB * HID) {
        int b = t / HID, j = t % HID;
        float s = 0.f;
#pragma unroll
        for (int c = 0; c < NC; c++) s += sp[b * NC + c] * sf1[j * NC + c];
        sh[b][j] = s >= 0.f ? s : SLOPE * s;
    }
    __syncthreads();
    if (t < NB) {
        int b = t;
        float lg[NK];
        float m = -1e30f;
#pragma unroll
        for (int k = 0; k < NK; k++) {
            float s = fc2b[k];
#pragma unroll
            for (int j = 0; j < HID; j++) s += sh[b][j] * fc2[k * HID + j];
            lg[k] = s / TEMP;
            m = fmaxf(m, lg[k]);
        }
        float den = 0.f, e[NK];
#pragma unroll
        for (int k = 0; k < NK; k++) { e[k] = expf(lg[k] - m); den += e[k]; }
        float inv = 1.0f / den;
#pragma unroll
        for (int k = 0; k < NK; k++) g_att[b * NK + k] = e[k] * inv;
    }
}

// ---------------------------------------------------------------------------
// Kernel 3: aggregate weights -> fp16, layout [b][ky][o][kx][c]
// ---------------------------------------------------------------------------
__global__ void agg_kernel(const float* __restrict__ weight,  // [K][O][I][3][3]
                           const float* __restrict__ bias_k) {
    int idx = blockIdx.x * 256 + threadIdx.x;
    const int TOT = NB * 3 * NO * 3 * NC;  // 589824
    if (idx < TOT) {
        int c = idx & 63;
        int t1 = idx >> 6;
        int kx = t1 % 3; t1 /= 3;
        int o = t1 & 63; t1 >>= 6;
        int ky = t1 % 3;
        int b = t1 / 3;
        const int KS = NO * NC * 9;
        int wb = (o * NC + c) * 9 + ky * 3 + kx;
        float s = g_att[b * NK + 0] * weight[wb] +
                  g_att[b * NK + 1] * weight[wb + KS] +
                  g_att[b * NK + 2] * weight[wb + 2 * KS] +
                  g_att[b * NK + 3] * weight[wb + 3 * KS];
        g_awh[idx] = __float2half_rn(s);
    }
    if (idx < NB * NO) {
        int b = idx >> 6, o = idx & 63;
        float s = 0.f;
#pragma unroll
        for (int k = 0; k < NK; k++) s += g_att[b * NK + k] * bias_k[k * NO + o];
        g_aggb[idx] = s;
    }
}

// ---------------------------------------------------------------------------
// Kernel 4: mma.sync fp16 conv. 512 thr, warp grid 8m x 2n.
// CTA = (b, 4-row group, half): 4 output rows x 128 px x 64 out.
// X: 6 staged rows (SW128); all 3 ky B planes resident; ONE barrier.
// kc-outer: 6 B x4 + 6 A x4 per kc feed 48 MMAs (4 rows).
// ---------------------------------------------------------------------------
#define XPLANE (6 * 130 * 128)            // 99840 B
#define OFF_B XPLANE
#define BSTR 400                          // bytes per o-row (192*2 + 16 pad)
#define BPL (64 * BSTR)                   // 25600 B per ky plane
#define CONV_SMEM (OFF_B + 3 * BPL)       // 176640 B

__global__ void __launch_bounds__(512, 1)
conv_kernel(float* __restrict__ out) {
    extern __shared__ char smem[];
    const unsigned sb = smem_u32(smem);
    const int tid = threadIdx.x;
    const int lane = tid & 31, wid = tid >> 5;
    const int wm = wid & 7, wn = wid >> 3;   // 8m x 2n
    const int b = blockIdx.y;
    const int y0 = (blockIdx.x >> 1) * 4;    // first of 4 output rows
    const int x0 = (blockIdx.x & 1) * 128;

    // ---- stage X (6 rows x 130 px x 128B, swizzled) ----
    {
        const size_t bbase = (size_t)b * NH * NW * NC;
        for (int i = tid; i < 6240; i += 512) {
            int ch = i & 7;
            int rc = i >> 3;                    // r*130 + cl, r in [0,6)
            int r = rc / 130, cl = rc - r * 130;
            int gy = y0 - 1 + r, gx = x0 - 1 + cl;
            bool ok = ((unsigned)gy < 256u) && ((unsigned)gx < 256u);
            const void* src = g_xh + bbase +
                              ((size_t)(ok ? (gy * 256 + gx) : 0) * 64) + ch * 8;
            unsigned o = (unsigned)(rc * 128 + ch * 16);
            cp16z(sb + sw128(o), src, ok ? 16 : 0);
        }
    }
    // ---- stage B: all 3 ky planes (4608 chunks of 16B) ----
    {
        const __half* awh = g_awh + (size_t)(b * 3) * (NO * 192);
#pragma unroll
        for (int j = 0; j < 9; j++) {
            int q = tid + j * 512;
            int o = q / 24, ck = q - o * 24;   // o in [0,192): ky*64 + och
            const void* src = awh + o * 192 + ck * 8;
            unsigned dst = sb + OFF_B + o * BSTR + ck * 16;
            cp16(dst, src);
        }
        asm volatile("cp.async.commit_group;");
    }
    asm volatile("cp.async.wait_group 0;");
    __syncthreads();  // the only barrier in the kernel

    float acc[4][4][4];  // [rw][tn][frag]
#pragma unroll
    for (int rw = 0; rw < 4; rw++)
#pragma unroll
        for (int tn = 0; tn < 4; tn++)
#pragma unroll
            for (int r = 0; r < 4; r++) acc[rw][tn][r] = 0.f;

    // A lane addressing (m16 x k16 tile per x4)
    const int apx = wm * 16 + (lane & 15);
    const unsigned aklo = (lane & 16) ? 16u : 0u;
    // B lane addressing (n16 x k16 per x4; two n-groups for n=32)
    const int bq = lane >> 3;
    const int brow = ((bq & 2) << 2) + (lane & 7);
    const unsigned bklo = (unsigned)((bq & 1) * 16);
    const unsigned brbase = sb + OFF_B + (unsigned)((wn * 32 + brow) * BSTR) + bklo;

#pragma unroll 1
    for (int kc = 0; kc < 12; kc++) {
        // Load all B fragments for this kc: 3 ky x 2 n-groups
        unsigned B0[3][4], B1[3][4];
#pragma unroll
        for (int ky = 0; ky < 3; ky++) {
            unsigned b0 = brbase + (unsigned)(ky * BPL) + kc * 32;
            ldmatrix_x4(B0[ky][0], B0[ky][1], B0[ky][2], B0[ky][3], b0);
            ldmatrix_x4(B1[ky][0], B1[ky][1], B1[ky][2], B1[ky][3], b0 + 16 * BSTR);
        }
        // Each x-row loaded once; contributes to out rows rw = r - ky in [0,4)
#pragma unroll
        for (int r = 0; r < 6; r++) {
            unsigned o_ = (unsigned)((r * 130 + apx) * 128 + kc * 32) + aklo;
            unsigned hc[4];
            ldmatrix_x4(hc[0], hc[1], hc[2], hc[3], sb + sw128(o_));
#pragma unroll
            for (int ky = 0; ky < 3; ky++) {
                const int rw = r - ky;
                if (rw >= 0 && rw < 4) {
                    mma16816(acc[rw][0], hc, B0[ky][0], B0[ky][1]);
                    mma16816(acc[rw][1], hc, B0[ky][2], B0[ky][3]);
                    mma16816(acc[rw][2], hc, B1[ky][0], B1[ky][1]);
                    mma16816(acc[rw][3], hc, B1[ky][2], B1[ky][3]);
                }
            }
        }
    }

    // ---- epilogue: bias + store (4 rows) ----
    const int m0 = x0 + wm * 16 + (lane >> 2);
#pragma unroll
    for (int rw = 0; rw < 4; rw++) {
        const int y = y0 + rw;
#pragma unroll
        for (int tn = 0; tn < 4; tn++) {
            int n0 = wn * 32 + tn * 8 + (lane & 3) * 2;
            float bv0 = g_aggb[b * NO + n0];
            float bv1 = g_aggb[b * NO + n0 + 1];
            size_t p0 = ((size_t)(b * NO + n0) * NH + y) * NW;
            size_t p1 = ((size_t)(b * NO + n0 + 1) * NH + y) * NW;
            out[p0 + m0] = acc[rw][tn][0] + bv0;
            out[p1 + m0] = acc[rw][tn][1] + bv1;
            out[p0 + m0 + 8] = acc[rw][tn][2] + bv0;
            out[p1 + m0 + 8] = acc[rw][tn][3] + bv1;
        }
    }
}

// ---------------------------------------------------------------------------
extern "C" void kernel_launch(void* const* d_in, const int* in_sizes, int n_in,
                              void* d_out, int out_size) {
    const float* x      = (const float*)d_in[0];
    const float* fc1_w  = (const float*)d_in[1];
    const float* fc2_w  = (const float*)d_in[2];
    const float* fc2_b  = (const float*)d_in[3];
    const float* weight = (const float*)d_in[4];
    const float* bias_k = (const float*)d_in[5];
    float* out = (float*)d_out;

    cudaFuncSetAttribute(split_kernel, cudaFuncAttributeMaxDynamicSharedMemorySize,
                         SPL_SMEM);
    cudaFuncSetAttribute(conv_kernel, cudaFuncAttributeMaxDynamicSharedMemorySize,
                         CONV_SMEM);

    split_kernel<<<NB * NH, 256, SPL_SMEM>>>(x);
    att_kernel<<<1, 288>>>(fc1_w, fc2_w, fc2_b);
    agg_kernel<<<(NB * 3 * NO * 3 * NC + 255) / 256, 256>>>(weight, bias_k);
    conv_kernel<<<dim3((NH / 4) * 2, NB), 512, CONV_SMEM>>>(out);
}